// round 2
// baseline (speedup 1.0000x reference)
#include <cuda_runtime.h>

#define NN 65536
#define KK 16
#define CC 64
#define C8 8
#define EE (NN*KK)
#define BNEPS 1e-5f

// ---- persistent scratch (device globals; no allocation) ----
__device__ double g_sum[6*64];
__device__ double g_ssq[6*64];
__device__ float  g_scl[6*64];   // per-slot BN scale
__device__ float  g_bia[6*64];   // per-slot BN bias
// slots: 0 bn1(C) | 1 posBN(3) | 2 attn_bn1(C) | 3 attn_bn2(8) | 4 bn2(C) | 5 bn3(C)

__device__ float g_t   [NN*CC];  // x @ W_in^T
__device__ float g_asrc[NN*CC];
__device__ float g_adst[NN*CC];
__device__ float g_hW  [NN*CC];
__device__ float g_aggr[NN*CC];  // aggregated messages
__device__ float g_t3  [NN*CC];  // h2 @ W_out^T
__device__ float g_a1  [EE*C8];

// ---------------------------------------------------------------------------
__global__ void k_zero() {
    int i = threadIdx.x;
    if (i < 384) { g_sum[i] = 0.0; g_ssq[i] = 0.0; }
}

__global__ void k_finalize(int slot, const float* __restrict__ g,
                           const float* __restrict__ b, float invCnt, int nch) {
    int c = threadIdx.x;
    if (c < nch) {
        float mu  = (float)(g_sum[slot*64+c] * (double)invCnt);
        float var = (float)(g_ssq[slot*64+c] * (double)invCnt) - mu*mu;
        float sc  = g[c] * rsqrtf(var + BNEPS);
        g_scl[slot*64+c] = sc;
        g_bia[slot*64+c] = b[c] - mu*sc;
    }
}

// ---------------------------------------------------------------------------
// Generic 64-wide GEMM: out[n][o] = f(in[n][:]) . W[o][:] + bias[o]
// f = optional BN(pre slot)+ReLU applied per input channel.
// Optional output stats accumulation into slot `stat`.
__global__ void k_gemm(const float* __restrict__ in, const float* __restrict__ W,
                       const float* __restrict__ bias, int pre, int stat,
                       float* __restrict__ out) {
    __shared__ float shW[64][65];   // shW[k][o] = W[o][k]
    __shared__ float shT[64][65];
    __shared__ float shS[2][64];
    int tid = threadIdx.x;
    int row0 = blockIdx.x * 64;

    for (int idx = tid; idx < 4096; idx += 256)
        shW[idx & 63][idx >> 6] = W[idx];
    for (int idx = tid; idx < 4096; idx += 256) {
        int r = idx >> 6, i = idx & 63;
        float v = in[(row0 + r)*64 + i];
        if (pre >= 0) v = fmaxf(fmaf(v, g_scl[pre*64+i], g_bia[pre*64+i]), 0.f);
        shT[r][i] = v;
    }
    if (tid < 128) shS[tid>>6][tid&63] = 0.f;
    __syncthreads();

    int r0 = (tid >> 4) << 2;
    int c0 = (tid & 15) << 2;
    float acc[4][4] = {};
    #pragma unroll 8
    for (int k = 0; k < 64; k++) {
        float a0 = shT[r0+0][k], a1 = shT[r0+1][k];
        float a2 = shT[r0+2][k], a3 = shT[r0+3][k];
        float b0 = shW[k][c0+0], b1 = shW[k][c0+1];
        float b2 = shW[k][c0+2], b3 = shW[k][c0+3];
        acc[0][0] = fmaf(a0,b0,acc[0][0]); acc[0][1] = fmaf(a0,b1,acc[0][1]);
        acc[0][2] = fmaf(a0,b2,acc[0][2]); acc[0][3] = fmaf(a0,b3,acc[0][3]);
        acc[1][0] = fmaf(a1,b0,acc[1][0]); acc[1][1] = fmaf(a1,b1,acc[1][1]);
        acc[1][2] = fmaf(a1,b2,acc[1][2]); acc[1][3] = fmaf(a1,b3,acc[1][3]);
        acc[2][0] = fmaf(a2,b0,acc[2][0]); acc[2][1] = fmaf(a2,b1,acc[2][1]);
        acc[2][2] = fmaf(a2,b2,acc[2][2]); acc[2][3] = fmaf(a2,b3,acc[2][3]);
        acc[3][0] = fmaf(a3,b0,acc[3][0]); acc[3][1] = fmaf(a3,b1,acc[3][1]);
        acc[3][2] = fmaf(a3,b2,acc[3][2]); acc[3][3] = fmaf(a3,b3,acc[3][3]);
    }
    float bb0=0.f, bb1=0.f, bb2=0.f, bb3=0.f;
    if (bias) { bb0=bias[c0]; bb1=bias[c0+1]; bb2=bias[c0+2]; bb3=bias[c0+3]; }
    float s0=0,s1=0,s2=0,s3=0, q0=0,q1=0,q2=0,q3=0;
    #pragma unroll
    for (int r = 0; r < 4; r++) {
        float v0=acc[r][0]+bb0, v1=acc[r][1]+bb1, v2=acc[r][2]+bb2, v3=acc[r][3]+bb3;
        float4 vv = make_float4(v0,v1,v2,v3);
        *(float4*)&out[(row0 + r0 + r)*64 + c0] = vv;
        s0+=v0; s1+=v1; s2+=v2; s3+=v3;
        q0+=v0*v0; q1+=v1*v1; q2+=v2*v2; q3+=v3*v3;
    }
    if (stat >= 0) {
        atomicAdd(&shS[0][c0+0], s0); atomicAdd(&shS[1][c0+0], q0);
        atomicAdd(&shS[0][c0+1], s1); atomicAdd(&shS[1][c0+1], q1);
        atomicAdd(&shS[0][c0+2], s2); atomicAdd(&shS[1][c0+2], q2);
        atomicAdd(&shS[0][c0+3], s3); atomicAdd(&shS[1][c0+3], q3);
        __syncthreads();
        if (tid < 64) {
            atomicAdd(&g_sum[stat*64+tid], (double)shS[0][tid]);
            atomicAdd(&g_ssq[stat*64+tid], (double)shS[1][tid]);
        }
    }
}

// ---------------------------------------------------------------------------
// Pass: stats of q = rel @ pos_w1^T + pos_b1 over E (3 channels)
__global__ void k_pos_stats(const float* __restrict__ pos, const int* __restrict__ src,
                            const float* __restrict__ pw1, const float* __restrict__ pb1) {
    float w00=pw1[0],w01=pw1[1],w02=pw1[2];
    float w10=pw1[3],w11=pw1[4],w12=pw1[5];
    float w20=pw1[6],w21=pw1[7],w22=pw1[8];
    float b0=pb1[0],b1=pb1[1],b2=pb1[2];
    float s0=0,s1=0,s2=0,q0=0,q1=0,q2=0;
    int stride = gridDim.x*blockDim.x;
    for (int e = blockIdx.x*blockDim.x + threadIdx.x; e < EE; e += stride) {
        int sj = src[e]; int di = e >> 4;
        float rx = pos[sj*3+0]-pos[di*3+0];
        float ry = pos[sj*3+1]-pos[di*3+1];
        float rz = pos[sj*3+2]-pos[di*3+2];
        float v0 = fmaf(rx,w00,fmaf(ry,w01,fmaf(rz,w02,b0)));
        float v1 = fmaf(rx,w10,fmaf(ry,w11,fmaf(rz,w12,b1)));
        float v2 = fmaf(rx,w20,fmaf(ry,w21,fmaf(rz,w22,b2)));
        s0+=v0; q0+=v0*v0; s1+=v1; q1+=v1*v1; s2+=v2; q2+=v2*v2;
    }
    __shared__ float sh[6];
    if (threadIdx.x < 6) sh[threadIdx.x]=0.f;
    __syncthreads();
    #pragma unroll
    for (int o = 16; o; o >>= 1) {
        s0+=__shfl_xor_sync(~0u,s0,o); s1+=__shfl_xor_sync(~0u,s1,o); s2+=__shfl_xor_sync(~0u,s2,o);
        q0+=__shfl_xor_sync(~0u,q0,o); q1+=__shfl_xor_sync(~0u,q1,o); q2+=__shfl_xor_sync(~0u,q2,o);
    }
    if ((threadIdx.x & 31) == 0) {
        atomicAdd(&sh[0],s0); atomicAdd(&sh[1],s1); atomicAdd(&sh[2],s2);
        atomicAdd(&sh[3],q0); atomicAdd(&sh[4],q1); atomicAdd(&sh[5],q2);
    }
    __syncthreads();
    if (threadIdx.x < 3) {
        atomicAdd(&g_sum[64+threadIdx.x], (double)sh[threadIdx.x]);
        atomicAdd(&g_ssq[64+threadIdx.x], (double)sh[threadIdx.x+3]);
    }
}

// ---------------------------------------------------------------------------
// Pass: stats of a = a_src[src] - a_dst[dst] + delta over E (64 channels).
// One warp per node (16 edges); lane handles channels (lane, lane+32).
__global__ void k_attn1_stats(const float* __restrict__ pos, const int* __restrict__ src,
                              const float* __restrict__ pw1, const float* __restrict__ pb1,
                              const float* __restrict__ pw2, const float* __restrict__ pb2) {
    int tid = threadIdx.x, lane = tid & 31, w = tid >> 5;
    int warpG = blockIdx.x*8 + w;
    int c = lane, c2 = lane + 32;
    float w00=pw1[0],w01=pw1[1],w02=pw1[2];
    float w10=pw1[3],w11=pw1[4],w12=pw1[5];
    float w20=pw1[6],w21=pw1[7],w22=pw1[8];
    float b0=pb1[0],b1=pb1[1],b2=pb1[2];
    float ps0=g_scl[64+0],ps1=g_scl[64+1],ps2=g_scl[64+2];
    float pB0=g_bia[64+0],pB1=g_bia[64+1],pB2=g_bia[64+2];
    float A0=pw2[c*3+0],A1=pw2[c*3+1],A2=pw2[c*3+2],Ab=pb2[c];
    float B0=pw2[c2*3+0],B1=pw2[c2*3+1],B2=pw2[c2*3+2],Bb=pb2[c2];
    float s=0,ss=0,t=0,tt=0;
    for (int n = warpG; n < NN; n += 8192) {
        float adc  = g_adst[n*64+c];
        float adc2 = g_adst[n*64+c2];
        float pix=pos[n*3],piy=pos[n*3+1],piz=pos[n*3+2];
        int sv = src[n*16 + (lane & 15)];
        #pragma unroll 4
        for (int j = 0; j < 16; j++) {
            int sj = __shfl_sync(~0u, sv, j);
            float rx=pos[sj*3]-pix, ry=pos[sj*3+1]-piy, rz=pos[sj*3+2]-piz;
            float d0 = fmaxf(fmaf(fmaf(rx,w00,fmaf(ry,w01,fmaf(rz,w02,b0))), ps0, pB0), 0.f);
            float d1 = fmaxf(fmaf(fmaf(rx,w10,fmaf(ry,w11,fmaf(rz,w12,b1))), ps1, pB1), 0.f);
            float d2 = fmaxf(fmaf(fmaf(rx,w20,fmaf(ry,w21,fmaf(rz,w22,b2))), ps2, pB2), 0.f);
            float a  = g_asrc[sj*64+c]  - adc  + fmaf(d0,A0,fmaf(d1,A1,fmaf(d2,A2,Ab)));
            float a2 = g_asrc[sj*64+c2] - adc2 + fmaf(d0,B0,fmaf(d1,B1,fmaf(d2,B2,Bb)));
            s+=a; ss+=a*a; t+=a2; tt+=a2*a2;
        }
    }
    __shared__ float sh[2][64];
    if (tid < 128) sh[tid>>6][tid&63]=0.f;
    __syncthreads();
    atomicAdd(&sh[0][c], s);  atomicAdd(&sh[1][c], ss);
    atomicAdd(&sh[0][c2], t); atomicAdd(&sh[1][c2], tt);
    __syncthreads();
    if (tid < 64) {
        atomicAdd(&g_sum[2*64+tid], (double)sh[0][tid]);
        atomicAdd(&g_ssq[2*64+tid], (double)sh[1][tid]);
    }
}

// ---------------------------------------------------------------------------
// Pass: a1 = relu(bn(a)) @ attn_w1^T + attn_b1 -> g_a1 [E,8]; stats for attn_bn2.
__global__ void k_a1(const float* __restrict__ pos, const int* __restrict__ src,
                     const float* __restrict__ pw1, const float* __restrict__ pb1,
                     const float* __restrict__ pw2, const float* __restrict__ pb2,
                     const float* __restrict__ aw1, const float* __restrict__ ab1) {
    __shared__ float shA[8][64];
    int tid = threadIdx.x, lane = tid & 31, w = tid >> 5;
    int warpG = blockIdx.x*8 + w;
    int c = lane, c2 = lane + 32;
    float w00=pw1[0],w01=pw1[1],w02=pw1[2];
    float w10=pw1[3],w11=pw1[4],w12=pw1[5];
    float w20=pw1[6],w21=pw1[7],w22=pw1[8];
    float b0=pb1[0],b1=pb1[1],b2=pb1[2];
    float ps0=g_scl[64+0],ps1=g_scl[64+1],ps2=g_scl[64+2];
    float pB0=g_bia[64+0],pB1=g_bia[64+1],pB2=g_bia[64+2];
    float A0=pw2[c*3+0],A1=pw2[c*3+1],A2=pw2[c*3+2],Ab=pb2[c];
    float B0=pw2[c2*3+0],B1=pw2[c2*3+1],B2=pw2[c2*3+2],Bb=pb2[c2];
    float s1c=g_scl[128+c], n1c=g_bia[128+c];
    float s1c2=g_scl[128+c2], n1c2=g_bia[128+c2];
    int jj = lane & 7, p = lane >> 3;
    float w1r[16];
    #pragma unroll
    for (int i = 0; i < 16; i++) w1r[i] = aw1[jj*64 + p*16 + i];
    float b1j = ab1[jj];
    float st=0, sq=0;
    for (int n = warpG; n < NN; n += 8192) {
        float adc  = g_adst[n*64+c];
        float adc2 = g_adst[n*64+c2];
        float pix=pos[n*3],piy=pos[n*3+1],piz=pos[n*3+2];
        int sv = src[n*16 + (lane & 15)];
        for (int j = 0; j < 16; j++) {
            int sj = __shfl_sync(~0u, sv, j);
            float rx=pos[sj*3]-pix, ry=pos[sj*3+1]-piy, rz=pos[sj*3+2]-piz;
            float d0 = fmaxf(fmaf(fmaf(rx,w00,fmaf(ry,w01,fmaf(rz,w02,b0))), ps0, pB0), 0.f);
            float d1 = fmaxf(fmaf(fmaf(rx,w10,fmaf(ry,w11,fmaf(rz,w12,b1))), ps1, pB1), 0.f);
            float d2 = fmaxf(fmaf(fmaf(rx,w20,fmaf(ry,w21,fmaf(rz,w22,b2))), ps2, pB2), 0.f);
            float a  = g_asrc[sj*64+c]  - adc  + fmaf(d0,A0,fmaf(d1,A1,fmaf(d2,A2,Ab)));
            float a2 = g_asrc[sj*64+c2] - adc2 + fmaf(d0,B0,fmaf(d1,B1,fmaf(d2,B2,Bb)));
            shA[w][c]  = fmaxf(fmaf(a,  s1c,  n1c ), 0.f);
            shA[w][c2] = fmaxf(fmaf(a2, s1c2, n1c2), 0.f);
            __syncwarp();
            float part = 0.f;
            #pragma unroll
            for (int i = 0; i < 16; i++) part = fmaf(shA[w][p*16+i], w1r[i], part);
            part += __shfl_xor_sync(~0u, part, 8);
            part += __shfl_xor_sync(~0u, part, 16);
            if (lane < 8) {
                float v = part + b1j;
                g_a1[(n*16+j)*8 + lane] = v;
                st += v; sq += v*v;
            }
            __syncwarp();
        }
    }
    __shared__ float shS[2][8];
    if (tid < 16) shS[tid>>3][tid&7] = 0.f;
    __syncthreads();
    if (lane < 8) { atomicAdd(&shS[0][lane], st); atomicAdd(&shS[1][lane], sq); }
    __syncthreads();
    if (tid < 8) {
        atomicAdd(&g_sum[3*64+tid], (double)shS[0][tid]);
        atomicAdd(&g_ssq[3*64+tid], (double)shS[1][tid]);
    }
}

// ---------------------------------------------------------------------------
// Aggregation: a2 = relu(bn2(a1)) @ attn_w2^T + b2 ; segment softmax (16 edges);
// out[i] = sum_e alpha[e][c%8] * (hW[src]+delta)[c]. Stats for bn2.
__global__ void k_aggr(const float* __restrict__ pos, const int* __restrict__ src,
                       const float* __restrict__ pw1, const float* __restrict__ pb1,
                       const float* __restrict__ pw2, const float* __restrict__ pb2,
                       const float* __restrict__ aw2, const float* __restrict__ ab2) {
    __shared__ float sh_b[4][16][8];
    __shared__ float sh_a2[4][16][8];
    __shared__ float sh_d[4][16][3];
    __shared__ int   sh_s[4][16];
    __shared__ float sh_w2[64];
    __shared__ float sh_b2[8];
    __shared__ float shS[2][64];
    int tid = threadIdx.x;
    int grp = tid >> 6, t = tid & 63;
    if (tid < 64) sh_w2[tid] = aw2[tid];
    if (tid < 8)  sh_b2[tid] = ab2[tid];
    if (tid < 128) shS[tid>>6][tid&63] = 0.f;
    float A0=pw2[t*3+0], A1=pw2[t*3+1], A2=pw2[t*3+2], Ab=pb2[t];
    float sA = g_scl[192 + (t & 7)], bA = g_bia[192 + (t & 7)];
    float w00=pw1[0],w01=pw1[1],w02=pw1[2];
    float w10=pw1[3],w11=pw1[4],w12=pw1[5];
    float w20=pw1[6],w21=pw1[7],w22=pw1[8];
    float b0=pb1[0],b1=pb1[1],b2=pb1[2];
    float ps0=g_scl[64+0],ps1=g_scl[64+1],ps2=g_scl[64+2];
    float pB0=g_bia[64+0],pB1=g_bia[64+1],pB2=g_bia[64+2];
    float st=0, sq=0;
    for (int it = 0; it < 16; it++) {
        int n = blockIdx.x*4 + grp + it*4096;
        if (t < 16) {
            int sj = src[n*16 + t];
            sh_s[grp][t] = sj;
            float pix=pos[n*3],piy=pos[n*3+1],piz=pos[n*3+2];
            float rx=pos[sj*3]-pix, ry=pos[sj*3+1]-piy, rz=pos[sj*3+2]-piz;
            sh_d[grp][t][0] = fmaxf(fmaf(fmaf(rx,w00,fmaf(ry,w01,fmaf(rz,w02,b0))), ps0, pB0), 0.f);
            sh_d[grp][t][1] = fmaxf(fmaf(fmaf(rx,w10,fmaf(ry,w11,fmaf(rz,w12,b1))), ps1, pB1), 0.f);
            sh_d[grp][t][2] = fmaxf(fmaf(fmaf(rx,w20,fmaf(ry,w21,fmaf(rz,w22,b2))), ps2, pB2), 0.f);
        }
        {
            int e = t >> 3, j = t & 7;
            float v = g_a1[(n*16+e)*8 + j];
            sh_b[grp][e][j] = fmaxf(fmaf(v, sA, bA), 0.f);
            int e2 = (t + 64) >> 3;
            float v2 = g_a1[(n*16+e2)*8 + j];
            sh_b[grp][e2][j] = fmaxf(fmaf(v2, sA, bA), 0.f);
        }
        __syncthreads();
        {
            int e = t >> 3, j = t & 7;
            float acc = sh_b2[j];
            #pragma unroll
            for (int m = 0; m < 8; m++) acc = fmaf(sh_b[grp][e][m], sh_w2[j*8+m], acc);
            sh_a2[grp][e][j] = acc;
            int e2 = (t + 64) >> 3;
            float acc2 = sh_b2[j];
            #pragma unroll
            for (int m = 0; m < 8; m++) acc2 = fmaf(sh_b[grp][e2][m], sh_w2[j*8+m], acc2);
            sh_a2[grp][e2][j] = acc2;
        }
        __syncthreads();
        if (t < 8) {
            float mx = -1e30f;
            #pragma unroll
            for (int e = 0; e < 16; e++) mx = fmaxf(mx, sh_a2[grp][e][t]);
            float ex[16]; float sum = 0.f;
            #pragma unroll
            for (int e = 0; e < 16; e++) { ex[e] = __expf(sh_a2[grp][e][t]-mx); sum += ex[e]; }
            float inv = 1.f/sum;
            #pragma unroll
            for (int e = 0; e < 16; e++) sh_a2[grp][e][t] = ex[e]*inv;
        }
        __syncthreads();
        {
            float acc = 0.f;
            int j8 = t & 7;
            #pragma unroll
            for (int e = 0; e < 16; e++) {
                int sj = sh_s[grp][e];
                float hw = g_hW[sj*64 + t];
                float delta = fmaf(sh_d[grp][e][0],A0,
                              fmaf(sh_d[grp][e][1],A1,
                              fmaf(sh_d[grp][e][2],A2, Ab)));
                acc = fmaf(sh_a2[grp][e][j8], hw + delta, acc);
            }
            g_aggr[n*64 + t] = acc;
            st += acc; sq += acc*acc;
        }
        __syncthreads();
    }
    atomicAdd(&shS[0][t], st); atomicAdd(&shS[1][t], sq);
    __syncthreads();
    if (tid < 64) {
        atomicAdd(&g_sum[4*64+tid], (double)shS[0][tid]);
        atomicAdd(&g_ssq[4*64+tid], (double)shS[1][tid]);
    }
}

// ---------------------------------------------------------------------------
__global__ void k_final(const float* __restrict__ x, float* __restrict__ out) {
    int idx = blockIdx.x*blockDim.x + threadIdx.x;
    int c = idx & 63;
    float v = fmaf(g_t3[idx], g_scl[5*64+c], g_bia[5*64+c]) + x[idx];
    out[idx] = fmaxf(v, 0.f);
}

// ---------------------------------------------------------------------------
extern "C" void kernel_launch(void* const* d_in, const int* in_sizes, int n_in,
                              void* d_out, int out_size) {
    const float* x      = (const float*)d_in[0];
    const float* pos    = (const float*)d_in[1];
    const int*   src    = (const int*)  d_in[2];   // edge_index[0]; dst = e/K by construction
    const float* W_in   = (const float*)d_in[3];
    const float* W_out  = (const float*)d_in[4];
    const float* pw1    = (const float*)d_in[5];
    const float* pb1    = (const float*)d_in[6];
    const float* pbn_g  = (const float*)d_in[7];
    const float* pbn_b  = (const float*)d_in[8];
    const float* pw2    = (const float*)d_in[9];
    const float* pb2    = (const float*)d_in[10];
    const float* abn1_g = (const float*)d_in[11];
    const float* abn1_b = (const float*)d_in[12];
    const float* aw1    = (const float*)d_in[13];
    const float* ab1    = (const float*)d_in[14];
    const float* abn2_g = (const float*)d_in[15];
    const float* abn2_b = (const float*)d_in[16];
    const float* aw2    = (const float*)d_in[17];
    const float* ab2    = (const float*)d_in[18];
    const float* lin_w  = (const float*)d_in[19];
    const float* lin_b  = (const float*)d_in[20];
    const float* src_w  = (const float*)d_in[21];
    const float* src_b  = (const float*)d_in[22];
    const float* dst_w  = (const float*)d_in[23];
    const float* dst_b  = (const float*)d_in[24];
    const float* bn1_g  = (const float*)d_in[25];
    const float* bn1_b  = (const float*)d_in[26];
    const float* bn2_g  = (const float*)d_in[27];
    const float* bn2_b  = (const float*)d_in[28];
    const float* bn3_g  = (const float*)d_in[29];
    const float* bn3_b  = (const float*)d_in[30];
    float* out = (float*)d_out;

    float *p_t, *p_asrc, *p_adst, *p_hW, *p_aggr, *p_t3;
    cudaGetSymbolAddress((void**)&p_t,    g_t);
    cudaGetSymbolAddress((void**)&p_asrc, g_asrc);
    cudaGetSymbolAddress((void**)&p_adst, g_adst);
    cudaGetSymbolAddress((void**)&p_hW,   g_hW);
    cudaGetSymbolAddress((void**)&p_aggr, g_aggr);
    cudaGetSymbolAddress((void**)&p_t3,   g_t3);

    k_zero<<<1,384>>>();

    // t = x @ W_in^T  (+ bn1 stats)
    k_gemm<<<1024,256>>>(x, W_in, nullptr, -1, 0, p_t);
    k_finalize<<<1,64>>>(0, bn1_g, bn1_b, 1.0f/NN, 64);

    // a_src/a_dst/hW = relu(bn1(t)) @ {src_w,dst_w,lin_w}^T + bias
    k_gemm<<<1024,256>>>(p_t, src_w, src_b, 0, -1, p_asrc);
    k_gemm<<<1024,256>>>(p_t, dst_w, dst_b, 0, -1, p_adst);
    k_gemm<<<1024,256>>>(p_t, lin_w, lin_b, 0, -1, p_hW);

    // pos BN stats over edges
    k_pos_stats<<<1024,256>>>(pos, src, pw1, pb1);
    k_finalize<<<1,64>>>(1, pbn_g, pbn_b, 1.0f/EE, 3);

    // attn_bn1 stats over edges
    k_attn1_stats<<<1024,256>>>(pos, src, pw1, pb1, pw2, pb2);
    k_finalize<<<1,64>>>(2, abn1_g, abn1_b, 1.0f/EE, 64);

    // a1 = relu(bn(a)) @ attn_w1^T + b1 ; attn_bn2 stats
    k_a1<<<1024,256>>>(pos, src, pw1, pb1, pw2, pb2, aw1, ab1);
    k_finalize<<<1,64>>>(3, abn2_g, abn2_b, 1.0f/EE, 8);

    // softmax + weighted aggregation ; bn2 stats
    k_aggr<<<1024,256>>>(pos, src, pw1, pb1, pw2, pb2, aw2, ab2);
    k_finalize<<<1,64>>>(4, bn2_g, bn2_b, 1.0f/NN, 64);

    // t3 = relu(bn2(aggr)) @ W_out^T ; bn3 stats
    k_gemm<<<1024,256>>>(p_aggr, W_out, nullptr, 4, 5, p_t3);
    k_finalize<<<1,64>>>(5, bn3_g, bn3_b, 1.0f/NN, 64);

    // y = relu(bn3(t3) + x)
    k_final<<<(NN*CC)/256,256>>>(x, out);
}

// round 3
// speedup vs baseline: 1.1327x; 1.1327x over previous
#include <cuda_runtime.h>

#define NN 65536
#define KK 16
#define CC 64
#define C8 8
#define EE (NN*KK)
#define BNEPS 1e-5f

// ---- persistent scratch ----
__device__ double g_sum[6*64];
__device__ double g_ssq[6*64];
__device__ float  g_scl[6*64];
__device__ float  g_bia[6*64];
// slots: 0 bn1 | 1 posBN(3) | 2 attn_bn1 | 3 attn_bn2(8) | 4 bn2 | 5 bn3

__device__ float g_t   [NN*CC];
__device__ float g_asrc[NN*CC];
__device__ float g_adst[NN*CC];
__device__ float g_hW  [NN*CC];
__device__ float g_aggr[NN*CC];
__device__ float g_t3  [NN*CC];
__device__ float g_a1  [EE*C8];
__device__ float g_pe  [3*EE];   // planar raw pos-MLP outputs

// ---------------------------------------------------------------------------
__global__ void k_zero() {
    int i = threadIdx.x;
    if (i < 384) { g_sum[i] = 0.0; g_ssq[i] = 0.0; }
}

__global__ void k_finalize(int slot, const float* __restrict__ g,
                           const float* __restrict__ b, float invCnt, int nch) {
    int c = threadIdx.x;
    if (c < nch) {
        float mu  = (float)(g_sum[slot*64+c] * (double)invCnt);
        float var = (float)(g_ssq[slot*64+c] * (double)invCnt) - mu*mu;
        float sc  = g[c] * rsqrtf(var + BNEPS);
        g_scl[slot*64+c] = sc;
        g_bia[slot*64+c] = b[c] - mu*sc;
    }
}

// ---------------------------------------------------------------------------
// 64-wide GEMM, 64-row tiles, 128 threads, 4 rows x 8 cols per thread.
__global__ __launch_bounds__(128) void k_gemm(
        const float* __restrict__ in, const float* __restrict__ W,
        const float* __restrict__ bias, int pre, int stat,
        float* __restrict__ out) {
    __shared__ __align__(16) float shT[64][68];
    __shared__ __align__(16) float shW[64][68];  // shW[k][o]
    __shared__ float shS[2][64];
    int tid = threadIdx.x;
    int row0 = blockIdx.x * 64;

    for (int idx = tid; idx < 4096; idx += 128)
        shW[idx & 63][idx >> 6] = W[idx];
    for (int idx = tid; idx < 1024; idx += 128) {
        int r = idx >> 4, i4 = (idx & 15) * 4;
        float4 v = *(const float4*)&in[(row0 + r)*64 + i4];
        if (pre >= 0) {
            float4 sc = *(const float4*)&g_scl[pre*64 + i4];
            float4 bi = *(const float4*)&g_bia[pre*64 + i4];
            v.x = fmaxf(fmaf(v.x, sc.x, bi.x), 0.f);
            v.y = fmaxf(fmaf(v.y, sc.y, bi.y), 0.f);
            v.z = fmaxf(fmaf(v.z, sc.z, bi.z), 0.f);
            v.w = fmaxf(fmaf(v.w, sc.w, bi.w), 0.f);
        }
        *(float4*)&shT[r][i4] = v;
    }
    if (tid < 128) shS[tid>>6][tid&63] = 0.f;
    __syncthreads();

    int r0 = (tid >> 3) * 4;
    int c0 = (tid & 7) * 8;
    float acc[4][8] = {};
    #pragma unroll 8
    for (int k = 0; k < 64; k++) {
        float4 b0 = *(float4*)&shW[k][c0];
        float4 b1 = *(float4*)&shW[k][c0+4];
        float av[4];
        av[0] = shT[r0+0][k]; av[1] = shT[r0+1][k];
        av[2] = shT[r0+2][k]; av[3] = shT[r0+3][k];
        #pragma unroll
        for (int r = 0; r < 4; r++) {
            acc[r][0] = fmaf(av[r], b0.x, acc[r][0]);
            acc[r][1] = fmaf(av[r], b0.y, acc[r][1]);
            acc[r][2] = fmaf(av[r], b0.z, acc[r][2]);
            acc[r][3] = fmaf(av[r], b0.w, acc[r][3]);
            acc[r][4] = fmaf(av[r], b1.x, acc[r][4]);
            acc[r][5] = fmaf(av[r], b1.y, acc[r][5]);
            acc[r][6] = fmaf(av[r], b1.z, acc[r][6]);
            acc[r][7] = fmaf(av[r], b1.w, acc[r][7]);
        }
    }
    float bb[8];
    #pragma unroll
    for (int j = 0; j < 8; j++) bb[j] = bias ? bias[c0+j] : 0.f;
    float s[8] = {}, q[8] = {};
    #pragma unroll
    for (int r = 0; r < 4; r++) {
        float v[8];
        #pragma unroll
        for (int j = 0; j < 8; j++) { v[j] = acc[r][j] + bb[j]; s[j] += v[j]; q[j] += v[j]*v[j]; }
        *(float4*)&out[(row0 + r0 + r)*64 + c0]   = make_float4(v[0],v[1],v[2],v[3]);
        *(float4*)&out[(row0 + r0 + r)*64 + c0+4] = make_float4(v[4],v[5],v[6],v[7]);
    }
    if (stat >= 0) {
        #pragma unroll
        for (int j = 0; j < 8; j++) {
            s[j] += __shfl_xor_sync(0xffffffffu, s[j], 8);
            s[j] += __shfl_xor_sync(0xffffffffu, s[j], 16);
            q[j] += __shfl_xor_sync(0xffffffffu, q[j], 8);
            q[j] += __shfl_xor_sync(0xffffffffu, q[j], 16);
        }
        if ((tid & 24) == 0) {
            #pragma unroll
            for (int j = 0; j < 8; j++) {
                atomicAdd(&shS[0][c0+j], s[j]);
                atomicAdd(&shS[1][c0+j], q[j]);
            }
        }
        __syncthreads();
        if (tid < 64) {
            atomicAdd(&g_sum[stat*64+tid], (double)shS[0][tid]);
            atomicAdd(&g_ssq[stat*64+tid], (double)shS[1][tid]);
        }
    }
}

// ---------------------------------------------------------------------------
// pos MLP (pre-BN) raw outputs -> g_pe ; stats for posBN (slot 1)
__global__ void k_pos_stats(const float* __restrict__ pos, const int* __restrict__ src,
                            const float* __restrict__ pw1, const float* __restrict__ pb1) {
    float w00=pw1[0],w01=pw1[1],w02=pw1[2];
    float w10=pw1[3],w11=pw1[4],w12=pw1[5];
    float w20=pw1[6],w21=pw1[7],w22=pw1[8];
    float b0=pb1[0],b1=pb1[1],b2=pb1[2];
    float s0=0,s1=0,s2=0,q0=0,q1=0,q2=0;
    int stride = gridDim.x*blockDim.x;
    for (int e = blockIdx.x*blockDim.x + threadIdx.x; e < EE; e += stride) {
        int sj = src[e]; int di = e >> 4;
        float rx = pos[sj*3+0]-pos[di*3+0];
        float ry = pos[sj*3+1]-pos[di*3+1];
        float rz = pos[sj*3+2]-pos[di*3+2];
        float v0 = fmaf(rx,w00,fmaf(ry,w01,fmaf(rz,w02,b0)));
        float v1 = fmaf(rx,w10,fmaf(ry,w11,fmaf(rz,w12,b1)));
        float v2 = fmaf(rx,w20,fmaf(ry,w21,fmaf(rz,w22,b2)));
        g_pe[e] = v0; g_pe[EE+e] = v1; g_pe[2*EE+e] = v2;
        s0+=v0; q0+=v0*v0; s1+=v1; q1+=v1*v1; s2+=v2; q2+=v2*v2;
    }
    __shared__ float sh[6];
    if (threadIdx.x < 6) sh[threadIdx.x]=0.f;
    __syncthreads();
    #pragma unroll
    for (int o = 16; o; o >>= 1) {
        s0+=__shfl_xor_sync(~0u,s0,o); s1+=__shfl_xor_sync(~0u,s1,o); s2+=__shfl_xor_sync(~0u,s2,o);
        q0+=__shfl_xor_sync(~0u,q0,o); q1+=__shfl_xor_sync(~0u,q1,o); q2+=__shfl_xor_sync(~0u,q2,o);
    }
    if ((threadIdx.x & 31) == 0) {
        atomicAdd(&sh[0],s0); atomicAdd(&sh[1],s1); atomicAdd(&sh[2],s2);
        atomicAdd(&sh[3],q0); atomicAdd(&sh[4],q1); atomicAdd(&sh[5],q2);
    }
    __syncthreads();
    if (threadIdx.x < 3) {
        atomicAdd(&g_sum[64+threadIdx.x], (double)sh[threadIdx.x]);
        atomicAdd(&g_ssq[64+threadIdx.x], (double)sh[threadIdx.x+3]);
    }
}

// ---------------------------------------------------------------------------
// stats of a = a_src[src] - a_dst[dst] + delta over E (slot 2).
// Half-warp per edge; lane handles 4 channels c4..c4+3.
__global__ __launch_bounds__(256) void k_attn1_stats(const int* __restrict__ src,
        const float* __restrict__ pw2, const float* __restrict__ pb2) {
    __shared__ float sh[2][64];
    int tid = threadIdx.x, lane = tid & 31;
    int l = lane & 15, hl = lane >> 4;
    int c4 = l * 4;
    float Ar[4][3], Ab[4];
    #pragma unroll
    for (int i = 0; i < 4; i++) {
        Ar[i][0]=pw2[(c4+i)*3]; Ar[i][1]=pw2[(c4+i)*3+1]; Ar[i][2]=pw2[(c4+i)*3+2];
        Ab[i]=pb2[c4+i];
    }
    float ps0=g_scl[64],ps1=g_scl[65],ps2=g_scl[66];
    float pB0=g_bia[64],pB1=g_bia[65],pB2=g_bia[66];
    float s[4]={}, q[4]={};
    int wId = (blockIdx.x*256 + tid) >> 5;
    int nW  = (gridDim.x*256) >> 5;
    for (int n = wId; n < NN; n += nW) {
        const float4 ad = *(const float4*)&g_adst[n*64 + c4];
        int sv = src[n*16 + l];
        #pragma unroll
        for (int jj = 0; jj < 8; jj++) {
            int ei = jj*2 + hl;
            int e  = n*16 + ei;
            int sj = __shfl_sync(0xffffffffu, sv, ei);
            float d0 = fmaxf(fmaf(g_pe[e],      ps0, pB0), 0.f);
            float d1 = fmaxf(fmaf(g_pe[EE+e],   ps1, pB1), 0.f);
            float d2 = fmaxf(fmaf(g_pe[2*EE+e], ps2, pB2), 0.f);
            const float4 as = *(const float4*)&g_asrc[sj*64 + c4];
            float a0 = as.x - ad.x + fmaf(d0,Ar[0][0],fmaf(d1,Ar[0][1],fmaf(d2,Ar[0][2],Ab[0])));
            float a1 = as.y - ad.y + fmaf(d0,Ar[1][0],fmaf(d1,Ar[1][1],fmaf(d2,Ar[1][2],Ab[1])));
            float a2 = as.z - ad.z + fmaf(d0,Ar[2][0],fmaf(d1,Ar[2][1],fmaf(d2,Ar[2][2],Ab[2])));
            float a3 = as.w - ad.w + fmaf(d0,Ar[3][0],fmaf(d1,Ar[3][1],fmaf(d2,Ar[3][2],Ab[3])));
            s[0]+=a0; q[0]+=a0*a0; s[1]+=a1; q[1]+=a1*a1;
            s[2]+=a2; q[2]+=a2*a2; s[3]+=a3; q[3]+=a3*a3;
        }
    }
    if (tid < 128) sh[tid>>6][tid&63] = 0.f;
    __syncthreads();
    #pragma unroll
    for (int i = 0; i < 4; i++) {
        s[i] += __shfl_xor_sync(0xffffffffu, s[i], 16);
        q[i] += __shfl_xor_sync(0xffffffffu, q[i], 16);
    }
    if (hl == 0) {
        #pragma unroll
        for (int i = 0; i < 4; i++) {
            atomicAdd(&sh[0][c4+i], s[i]);
            atomicAdd(&sh[1][c4+i], q[i]);
        }
    }
    __syncthreads();
    if (tid < 64) {
        atomicAdd(&g_sum[128+tid], (double)sh[0][tid]);
        atomicAdd(&g_ssq[128+tid], (double)sh[1][tid]);
    }
}

// ---------------------------------------------------------------------------
// a1 = relu(bn(a)) @ attn_w1^T + b1 -> g_a1 [E,8]; stats slot 3.
__global__ __launch_bounds__(256) void k_a1(const int* __restrict__ src,
        const float* __restrict__ pw2, const float* __restrict__ pb2,
        const float* __restrict__ aw1, const float* __restrict__ ab1) {
    __shared__ float sh[2][8];
    int tid = threadIdx.x, lane = tid & 31;
    int l = lane & 15, hl = lane >> 4;
    int c4 = l * 4;
    float Ar[4][3], Ab[4];
    #pragma unroll
    for (int i = 0; i < 4; i++) {
        Ar[i][0]=pw2[(c4+i)*3]; Ar[i][1]=pw2[(c4+i)*3+1]; Ar[i][2]=pw2[(c4+i)*3+2];
        Ab[i]=pb2[c4+i];
    }
    float ps0=g_scl[64],ps1=g_scl[65],ps2=g_scl[66];
    float pB0=g_bia[64],pB1=g_bia[65],pB2=g_bia[66];
    float sc[4], sb[4];
    #pragma unroll
    for (int i = 0; i < 4; i++) { sc[i]=g_scl[128+c4+i]; sb[i]=g_bia[128+c4+i]; }
    float4 w1v[8];
    #pragma unroll
    for (int j = 0; j < 8; j++) w1v[j] = *(const float4*)&aw1[j*64 + c4];
    float b1v[8];
    #pragma unroll
    for (int j = 0; j < 8; j++) b1v[j] = ab1[j];
    float st[8] = {}, sq[8] = {};
    int wId = (blockIdx.x*256 + tid) >> 5;
    int nW  = (gridDim.x*256) >> 5;
    for (int n = wId; n < NN; n += nW) {
        const float4 ad = *(const float4*)&g_adst[n*64 + c4];
        int sv = src[n*16 + l];
        #pragma unroll
        for (int jj = 0; jj < 8; jj++) {
            int ei = jj*2 + hl;
            int e  = n*16 + ei;
            int sj = __shfl_sync(0xffffffffu, sv, ei);
            float d0 = fmaxf(fmaf(g_pe[e],      ps0, pB0), 0.f);
            float d1 = fmaxf(fmaf(g_pe[EE+e],   ps1, pB1), 0.f);
            float d2 = fmaxf(fmaf(g_pe[2*EE+e], ps2, pB2), 0.f);
            const float4 as = *(const float4*)&g_asrc[sj*64 + c4];
            float a0 = as.x - ad.x + fmaf(d0,Ar[0][0],fmaf(d1,Ar[0][1],fmaf(d2,Ar[0][2],Ab[0])));
            float a1 = as.y - ad.y + fmaf(d0,Ar[1][0],fmaf(d1,Ar[1][1],fmaf(d2,Ar[1][2],Ab[1])));
            float a2 = as.z - ad.z + fmaf(d0,Ar[2][0],fmaf(d1,Ar[2][1],fmaf(d2,Ar[2][2],Ab[2])));
            float a3 = as.w - ad.w + fmaf(d0,Ar[3][0],fmaf(d1,Ar[3][1],fmaf(d2,Ar[3][2],Ab[3])));
            float r0 = fmaxf(fmaf(a0, sc[0], sb[0]), 0.f);
            float r1 = fmaxf(fmaf(a1, sc[1], sb[1]), 0.f);
            float r2 = fmaxf(fmaf(a2, sc[2], sb[2]), 0.f);
            float r3 = fmaxf(fmaf(a3, sc[3], sb[3]), 0.f);
            float p[8];
            #pragma unroll
            for (int j = 0; j < 8; j++)
                p[j] = fmaf(r0, w1v[j].x, fmaf(r1, w1v[j].y, fmaf(r2, w1v[j].z, r3 * w1v[j].w)));
            #pragma unroll
            for (int o = 8; o >= 1; o >>= 1) {
                #pragma unroll
                for (int j = 0; j < 8; j++) p[j] += __shfl_xor_sync(0xffffffffu, p[j], o);
            }
            if (l == 0) {
                float v[8];
                #pragma unroll
                for (int j = 0; j < 8; j++) { v[j] = p[j] + b1v[j]; st[j] += v[j]; sq[j] += v[j]*v[j]; }
                *(float4*)&g_a1[e*8]   = make_float4(v[0],v[1],v[2],v[3]);
                *(float4*)&g_a1[e*8+4] = make_float4(v[4],v[5],v[6],v[7]);
            }
        }
    }
    if (tid < 16) sh[tid>>3][tid&7] = 0.f;
    __syncthreads();
    #pragma unroll
    for (int j = 0; j < 8; j++) {
        st[j] += __shfl_xor_sync(0xffffffffu, st[j], 16);
        sq[j] += __shfl_xor_sync(0xffffffffu, sq[j], 16);
    }
    if (lane == 0) {
        #pragma unroll
        for (int j = 0; j < 8; j++) { atomicAdd(&sh[0][j], st[j]); atomicAdd(&sh[1][j], sq[j]); }
    }
    __syncthreads();
    if (tid < 8) {
        atomicAdd(&g_sum[192+tid], (double)sh[0][tid]);
        atomicAdd(&g_ssq[192+tid], (double)sh[1][tid]);
    }
}

// ---------------------------------------------------------------------------
// Warp-per-node: a2 from a1, softmax (16 edges), weighted aggregation; stats slot 4.
__global__ __launch_bounds__(256) void k_aggr(const int* __restrict__ src,
        const float* __restrict__ pw2, const float* __restrict__ pb2,
        const float* __restrict__ aw2, const float* __restrict__ ab2) {
    __shared__ float sh_alpha[8][16][8];
    __shared__ float sh_d[8][16][3];
    __shared__ float shS[2][64];
    int tid = threadIdx.x, lane = tid & 31, w = tid >> 5;
    int c = lane, c2 = lane + 32;
    float A0=pw2[c*3],  A1=pw2[c*3+1],  A2=pw2[c*3+2],  Abc=pb2[c];
    float B0=pw2[c2*3], B1=pw2[c2*3+1], B2=pw2[c2*3+2], Bbc=pb2[c2];
    float ps0=g_scl[64],ps1=g_scl[65],ps2=g_scl[66];
    float pB0=g_bia[64],pB1=g_bia[65],pB2=g_bia[66];
    int e = lane >> 1, j4 = (lane & 1) * 4;
    float s3[4], b3[4];
    #pragma unroll
    for (int i = 0; i < 4; i++) { s3[i]=g_scl[192+j4+i]; b3[i]=g_bia[192+j4+i]; }
    float4 w2v[8];
    #pragma unroll
    for (int j = 0; j < 8; j++) w2v[j] = *(const float4*)&aw2[j*8 + j4];
    float b2v[8];
    #pragma unroll
    for (int j = 0; j < 8; j++) b2v[j] = ab2[j];
    int j8 = lane & 7;
    float st=0, sq=0, st2=0, sq2=0;
    if (tid < 128) shS[tid>>6][tid&63] = 0.f;
    int wId = blockIdx.x*8 + w, nW = gridDim.x*8;
    for (int n = wId; n < NN; n += nW) {
        int sv = src[n*16 + (lane & 15)];
        if (lane < 16) {
            int ee = n*16 + lane;
            sh_d[w][lane][0] = fmaxf(fmaf(g_pe[ee],      ps0, pB0), 0.f);
            sh_d[w][lane][1] = fmaxf(fmaf(g_pe[EE+ee],   ps1, pB1), 0.f);
            sh_d[w][lane][2] = fmaxf(fmaf(g_pe[2*EE+ee], ps2, pB2), 0.f);
        }
        float4 bv = *(const float4*)&g_a1[n*128 + lane*4];
        float bb0 = fmaxf(fmaf(bv.x, s3[0], b3[0]), 0.f);
        float bb1 = fmaxf(fmaf(bv.y, s3[1], b3[1]), 0.f);
        float bb2 = fmaxf(fmaf(bv.z, s3[2], b3[2]), 0.f);
        float bb3 = fmaxf(fmaf(bv.w, s3[3], b3[3]), 0.f);
        float p[8];
        #pragma unroll
        for (int j = 0; j < 8; j++)
            p[j] = fmaf(bb0, w2v[j].x, fmaf(bb1, w2v[j].y, fmaf(bb2, w2v[j].z, bb3 * w2v[j].w)));
        #pragma unroll
        for (int j = 0; j < 8; j++) p[j] += __shfl_xor_sync(0xffffffffu, p[j], 1);
        if ((lane & 1) == 0) {
            #pragma unroll
            for (int j = 0; j < 8; j++) sh_alpha[w][e][j] = p[j] + b2v[j];
        }
        __syncwarp();
        if (lane < 8) {
            float mx = -1e30f;
            #pragma unroll
            for (int t = 0; t < 16; t++) mx = fmaxf(mx, sh_alpha[w][t][lane]);
            float ex[16], sm = 0.f;
            #pragma unroll
            for (int t = 0; t < 16; t++) { ex[t] = __expf(sh_alpha[w][t][lane]-mx); sm += ex[t]; }
            float inv = 1.f/sm;
            #pragma unroll
            for (int t = 0; t < 16; t++) sh_alpha[w][t][lane] = ex[t]*inv;
        }
        __syncwarp();
        float acc = 0.f, acc2 = 0.f;
        #pragma unroll
        for (int t = 0; t < 16; t++) {
            int sj = __shfl_sync(0xffffffffu, sv, t);
            float hw  = g_hW[sj*64 + c];
            float hw2 = g_hW[sj*64 + c2];
            float d0 = sh_d[w][t][0], d1 = sh_d[w][t][1], d2 = sh_d[w][t][2];
            float al = sh_alpha[w][t][j8];
            acc  = fmaf(al, hw  + fmaf(d0,A0,fmaf(d1,A1,fmaf(d2,A2,Abc))), acc);
            acc2 = fmaf(al, hw2 + fmaf(d0,B0,fmaf(d1,B1,fmaf(d2,B2,Bbc))), acc2);
        }
        g_aggr[n*64 + c]  = acc;
        g_aggr[n*64 + c2] = acc2;
        st += acc; sq += acc*acc; st2 += acc2; sq2 += acc2*acc2;
        __syncwarp();
    }
    __syncthreads();
    atomicAdd(&shS[0][c],  st);  atomicAdd(&shS[1][c],  sq);
    atomicAdd(&shS[0][c2], st2); atomicAdd(&shS[1][c2], sq2);
    __syncthreads();
    if (tid < 64) {
        atomicAdd(&g_sum[256+tid], (double)shS[0][tid]);
        atomicAdd(&g_ssq[256+tid], (double)shS[1][tid]);
    }
}

// ---------------------------------------------------------------------------
__global__ void k_final(const float* __restrict__ x, float* __restrict__ out) {
    int idx = blockIdx.x*blockDim.x + threadIdx.x;
    int c = idx & 63;
    float v = fmaf(g_t3[idx], g_scl[5*64+c], g_bia[5*64+c]) + x[idx];
    out[idx] = fmaxf(v, 0.f);
}

// ---------------------------------------------------------------------------
extern "C" void kernel_launch(void* const* d_in, const int* in_sizes, int n_in,
                              void* d_out, int out_size) {
    const float* x      = (const float*)d_in[0];
    const float* pos    = (const float*)d_in[1];
    const int*   src    = (const int*)  d_in[2];
    const float* W_in   = (const float*)d_in[3];
    const float* W_out  = (const float*)d_in[4];
    const float* pw1    = (const float*)d_in[5];
    const float* pb1    = (const float*)d_in[6];
    const float* pbn_g  = (const float*)d_in[7];
    const float* pbn_b  = (const float*)d_in[8];
    const float* pw2    = (const float*)d_in[9];
    const float* pb2    = (const float*)d_in[10];
    const float* abn1_g = (const float*)d_in[11];
    const float* abn1_b = (const float*)d_in[12];
    const float* aw1    = (const float*)d_in[13];
    const float* ab1    = (const float*)d_in[14];
    const float* abn2_g = (const float*)d_in[15];
    const float* abn2_b = (const float*)d_in[16];
    const float* aw2    = (const float*)d_in[17];
    const float* ab2    = (const float*)d_in[18];
    const float* lin_w  = (const float*)d_in[19];
    const float* lin_b  = (const float*)d_in[20];
    const float* src_w  = (const float*)d_in[21];
    const float* src_b  = (const float*)d_in[22];
    const float* dst_w  = (const float*)d_in[23];
    const float* dst_b  = (const float*)d_in[24];
    const float* bn1_g  = (const float*)d_in[25];
    const float* bn1_b  = (const float*)d_in[26];
    const float* bn2_g  = (const float*)d_in[27];
    const float* bn2_b  = (const float*)d_in[28];
    const float* bn3_g  = (const float*)d_in[29];
    const float* bn3_b  = (const float*)d_in[30];
    float* out = (float*)d_out;

    float *p_t, *p_asrc, *p_adst, *p_hW, *p_aggr, *p_t3;
    cudaGetSymbolAddress((void**)&p_t,    g_t);
    cudaGetSymbolAddress((void**)&p_asrc, g_asrc);
    cudaGetSymbolAddress((void**)&p_adst, g_adst);
    cudaGetSymbolAddress((void**)&p_hW,   g_hW);
    cudaGetSymbolAddress((void**)&p_aggr, g_aggr);
    cudaGetSymbolAddress((void**)&p_t3,   g_t3);

    k_zero<<<1,384>>>();

    // pos MLP raw outputs + posBN stats (independent of GEMMs)
    k_pos_stats<<<1024,256>>>(pos, src, pw1, pb1);
    k_finalize<<<1,64>>>(1, pbn_g, pbn_b, 1.0f/EE, 3);

    // t = x @ W_in^T  (+ bn1 stats)
    k_gemm<<<1024,128>>>(x, W_in, nullptr, -1, 0, p_t);
    k_finalize<<<1,64>>>(0, bn1_g, bn1_b, 1.0f/NN, 64);

    // a_src/a_dst/hW = relu(bn1(t)) @ {src_w,dst_w,lin_w}^T + bias
    k_gemm<<<1024,128>>>(p_t, src_w, src_b, 0, -1, p_asrc);
    k_gemm<<<1024,128>>>(p_t, dst_w, dst_b, 0, -1, p_adst);
    k_gemm<<<1024,128>>>(p_t, lin_w, lin_b, 0, -1, p_hW);

    // attn_bn1 stats over edges
    k_attn1_stats<<<512,256>>>(src, pw2, pb2);
    k_finalize<<<1,64>>>(2, abn1_g, abn1_b, 1.0f/EE, 64);

    // a1 ; attn_bn2 stats
    k_a1<<<512,256>>>(src, pw2, pb2, aw1, ab1);
    k_finalize<<<1,64>>>(3, abn2_g, abn2_b, 1.0f/EE, 8);

    // softmax + aggregation ; bn2 stats
    k_aggr<<<512,256>>>(src, pw2, pb2, aw2, ab2);
    k_finalize<<<1,64>>>(4, bn2_g, bn2_b, 1.0f/NN, 64);

    // t3 = relu(bn2(aggr)) @ W_out^T ; bn3 stats
    k_gemm<<<1024,128>>>(p_aggr, W_out, nullptr, 4, 5, p_t3);
    k_finalize<<<1,64>>>(5, bn3_g, bn3_b, 1.0f/NN, 64);

    // y = relu(bn3(t3) + x)
    k_final<<<(NN*CC)/256,256>>>(x, out);
}

// round 4
// speedup vs baseline: 1.2699x; 1.1211x over previous
#include <cuda_runtime.h>

#define NN 65536
#define KK 16
#define CC 64
#define C8 8
#define EE (NN*KK)
#define BNEPS 1e-5f

// ---- persistent scratch ----
__device__ double g_sum[6*64];
__device__ double g_ssq[6*64];
__device__ float  g_scl[6*64];
__device__ float  g_bia[6*64];
// slots: 0 bn1 | 1 posBN(3) | 2 attn_bn1 | 3 attn_bn2(8) | 4 bn2 | 5 bn3

__device__ float g_t   [NN*CC];
__device__ float g_asrc[NN*CC];
__device__ float g_adst[NN*CC];
__device__ float g_hW  [NN*CC];
__device__ float g_aggr[NN*CC];
__device__ float g_t3  [NN*CC];
__device__ float g_a1  [EE*C8];
__device__ float g_pe  [3*EE];   // planar raw pos-MLP outputs

// ---------------------------------------------------------------------------
__global__ void k_zero() {
    int i = threadIdx.x;
    if (i < 384) { g_sum[i] = 0.0; g_ssq[i] = 0.0; }
}

__global__ void k_finalize(int slot, const float* __restrict__ g,
                           const float* __restrict__ b, float invCnt, int nch) {
    int c = threadIdx.x;
    if (c < nch) {
        float mu  = (float)(g_sum[slot*64+c] * (double)invCnt);
        float var = (float)(g_ssq[slot*64+c] * (double)invCnt) - mu*mu;
        float sc  = g[c] * rsqrtf(var + BNEPS);
        g_scl[slot*64+c] = sc;
        g_bia[slot*64+c] = b[c] - mu*sc;
    }
}

// ---------------------------------------------------------------------------
// 64-wide GEMM: 128 rows/block, 128 threads, 8 rows x 8 cols per thread.
// Conflict-free smem: consecutive-row groups for A; quad-permuted W rows.
__global__ __launch_bounds__(128) void k_gemm(
        const float* __restrict__ in, const float* __restrict__ W,
        const float* __restrict__ bias, int pre, int stat,
        float* __restrict__ out) {
    __shared__ __align__(16) float shT[128][68];
    __shared__ __align__(16) float shW[64][68];   // quad-permuted within row
    __shared__ float shS[2][64];
    int tid = threadIdx.x;
    int row0 = blockIdx.x * 128;

    // W[o][k] -> shW[k][perm(o)], perm moves quad q -> (q>>1)+(q&1)*8
    for (int idx = tid; idx < 4096; idx += 128) {
        int o = idx >> 6, k = idx & 63;
        int q = o >> 2;
        int po = (((q >> 1) + ((q & 1) << 3)) << 2) + (o & 3);
        shW[k][po] = W[idx];
    }
    // input tile (optionally BN+ReLU)
    for (int idx = tid; idx < 2048; idx += 128) {
        int r = idx >> 4, i4 = (idx & 15) * 4;
        float4 v = *(const float4*)&in[(row0 + r)*64 + i4];
        if (pre >= 0) {
            float4 sc = *(const float4*)&g_scl[pre*64 + i4];
            float4 bi = *(const float4*)&g_bia[pre*64 + i4];
            v.x = fmaxf(fmaf(v.x, sc.x, bi.x), 0.f);
            v.y = fmaxf(fmaf(v.y, sc.y, bi.y), 0.f);
            v.z = fmaxf(fmaf(v.z, sc.z, bi.z), 0.f);
            v.w = fmaxf(fmaf(v.w, sc.w, bi.w), 0.f);
        }
        *(float4*)&shT[r][i4] = v;
    }
    shS[0][tid & 63] = 0.f;
    if (tid < 64) shS[1][tid] = 0.f;
    __syncthreads();

    int w = tid >> 5, lane = tid & 31;
    int g = lane >> 3, t = lane & 7;
    int rbase = w*32 + g;       // thread rows: rbase + 4*i, i=0..7
    int c0 = t * 8;             // logical cols c0..c0+7
    float acc[8][8] = {};
    #pragma unroll 4
    for (int k = 0; k < 64; k++) {
        // physical quad t -> logical cols c0..c0+3 ; quad t+8 -> c0+4..c0+7
        float4 b0 = *(float4*)&shW[k][t*4];
        float4 b1 = *(float4*)&shW[k][32 + t*4];
        float av[8];
        #pragma unroll
        for (int i = 0; i < 8; i++) av[i] = shT[rbase + 4*i][k];
        #pragma unroll
        for (int i = 0; i < 8; i++) {
            acc[i][0] = fmaf(av[i], b0.x, acc[i][0]);
            acc[i][1] = fmaf(av[i], b0.y, acc[i][1]);
            acc[i][2] = fmaf(av[i], b0.z, acc[i][2]);
            acc[i][3] = fmaf(av[i], b0.w, acc[i][3]);
            acc[i][4] = fmaf(av[i], b1.x, acc[i][4]);
            acc[i][5] = fmaf(av[i], b1.y, acc[i][5]);
            acc[i][6] = fmaf(av[i], b1.z, acc[i][6]);
            acc[i][7] = fmaf(av[i], b1.w, acc[i][7]);
        }
    }
    float bb[8];
    #pragma unroll
    for (int j = 0; j < 8; j++) bb[j] = bias ? bias[c0+j] : 0.f;
    float s[8] = {}, q[8] = {};
    #pragma unroll
    for (int i = 0; i < 8; i++) {
        int rr = row0 + rbase + 4*i;
        float v[8];
        #pragma unroll
        for (int j = 0; j < 8; j++) { v[j] = acc[i][j] + bb[j]; s[j] += v[j]; q[j] += v[j]*v[j]; }
        *(float4*)&out[rr*64 + c0]     = make_float4(v[0],v[1],v[2],v[3]);
        *(float4*)&out[rr*64 + c0 + 4] = make_float4(v[4],v[5],v[6],v[7]);
    }
    if (stat >= 0) {
        #pragma unroll
        for (int j = 0; j < 8; j++) {
            atomicAdd(&shS[0][c0+j], s[j]);
            atomicAdd(&shS[1][c0+j], q[j]);
        }
        __syncthreads();
        if (tid < 64) {
            atomicAdd(&g_sum[stat*64+tid], (double)shS[0][tid]);
            atomicAdd(&g_ssq[stat*64+tid], (double)shS[1][tid]);
        }
    }
}

// ---------------------------------------------------------------------------
// pos MLP (pre-BN) raw outputs -> g_pe ; stats for posBN (slot 1)
__global__ void k_pos_stats(const float* __restrict__ pos, const int* __restrict__ src,
                            const float* __restrict__ pw1, const float* __restrict__ pb1) {
    float w00=pw1[0],w01=pw1[1],w02=pw1[2];
    float w10=pw1[3],w11=pw1[4],w12=pw1[5];
    float w20=pw1[6],w21=pw1[7],w22=pw1[8];
    float b0=pb1[0],b1=pb1[1],b2=pb1[2];
    float s0=0,s1=0,s2=0,q0=0,q1=0,q2=0;
    int stride = gridDim.x*blockDim.x;
    for (int e = blockIdx.x*blockDim.x + threadIdx.x; e < EE; e += stride) {
        int sj = src[e]; int di = e >> 4;
        float rx = pos[sj*3+0]-pos[di*3+0];
        float ry = pos[sj*3+1]-pos[di*3+1];
        float rz = pos[sj*3+2]-pos[di*3+2];
        float v0 = fmaf(rx,w00,fmaf(ry,w01,fmaf(rz,w02,b0)));
        float v1 = fmaf(rx,w10,fmaf(ry,w11,fmaf(rz,w12,b1)));
        float v2 = fmaf(rx,w20,fmaf(ry,w21,fmaf(rz,w22,b2)));
        g_pe[e] = v0; g_pe[EE+e] = v1; g_pe[2*EE+e] = v2;
        s0+=v0; q0+=v0*v0; s1+=v1; q1+=v1*v1; s2+=v2; q2+=v2*v2;
    }
    __shared__ float sh[6];
    if (threadIdx.x < 6) sh[threadIdx.x]=0.f;
    __syncthreads();
    #pragma unroll
    for (int o = 16; o; o >>= 1) {
        s0+=__shfl_xor_sync(~0u,s0,o); s1+=__shfl_xor_sync(~0u,s1,o); s2+=__shfl_xor_sync(~0u,s2,o);
        q0+=__shfl_xor_sync(~0u,q0,o); q1+=__shfl_xor_sync(~0u,q1,o); q2+=__shfl_xor_sync(~0u,q2,o);
    }
    if ((threadIdx.x & 31) == 0) {
        atomicAdd(&sh[0],s0); atomicAdd(&sh[1],s1); atomicAdd(&sh[2],s2);
        atomicAdd(&sh[3],q0); atomicAdd(&sh[4],q1); atomicAdd(&sh[5],q2);
    }
    __syncthreads();
    if (threadIdx.x < 3) {
        atomicAdd(&g_sum[64+threadIdx.x], (double)sh[threadIdx.x]);
        atomicAdd(&g_ssq[64+threadIdx.x], (double)sh[threadIdx.x+3]);
    }
}

// ---------------------------------------------------------------------------
// stats of a = a_src[src] - a_dst[dst] + delta over E (slot 2).
__global__ __launch_bounds__(256) void k_attn1_stats(const int* __restrict__ src,
        const float* __restrict__ pw2, const float* __restrict__ pb2) {
    __shared__ float sh[2][64];
    int tid = threadIdx.x, lane = tid & 31;
    int l = lane & 15, hl = lane >> 4;
    int c4 = l * 4;
    float Ar[4][3], Ab[4];
    #pragma unroll
    for (int i = 0; i < 4; i++) {
        Ar[i][0]=pw2[(c4+i)*3]; Ar[i][1]=pw2[(c4+i)*3+1]; Ar[i][2]=pw2[(c4+i)*3+2];
        Ab[i]=pb2[c4+i];
    }
    float ps0=g_scl[64],ps1=g_scl[65],ps2=g_scl[66];
    float pB0=g_bia[64],pB1=g_bia[65],pB2=g_bia[66];
    float s[4]={}, q[4]={};
    int wId = (blockIdx.x*256 + tid) >> 5;
    int nW  = (gridDim.x*256) >> 5;
    for (int n = wId; n < NN; n += nW) {
        const float4 ad = *(const float4*)&g_adst[n*64 + c4];
        int sv = src[n*16 + l];
        #pragma unroll
        for (int jj = 0; jj < 8; jj++) {
            int ei = jj*2 + hl;
            int e  = n*16 + ei;
            int sj = __shfl_sync(0xffffffffu, sv, ei);
            float d0 = fmaxf(fmaf(g_pe[e],      ps0, pB0), 0.f);
            float d1 = fmaxf(fmaf(g_pe[EE+e],   ps1, pB1), 0.f);
            float d2 = fmaxf(fmaf(g_pe[2*EE+e], ps2, pB2), 0.f);
            const float4 as = *(const float4*)&g_asrc[sj*64 + c4];
            float a0 = as.x - ad.x + fmaf(d0,Ar[0][0],fmaf(d1,Ar[0][1],fmaf(d2,Ar[0][2],Ab[0])));
            float a1 = as.y - ad.y + fmaf(d0,Ar[1][0],fmaf(d1,Ar[1][1],fmaf(d2,Ar[1][2],Ab[1])));
            float a2 = as.z - ad.z + fmaf(d0,Ar[2][0],fmaf(d1,Ar[2][1],fmaf(d2,Ar[2][2],Ab[2])));
            float a3 = as.w - ad.w + fmaf(d0,Ar[3][0],fmaf(d1,Ar[3][1],fmaf(d2,Ar[3][2],Ab[3])));
            s[0]+=a0; q[0]+=a0*a0; s[1]+=a1; q[1]+=a1*a1;
            s[2]+=a2; q[2]+=a2*a2; s[3]+=a3; q[3]+=a3*a3;
        }
    }
    if (tid < 128) sh[tid>>6][tid&63] = 0.f;
    __syncthreads();
    #pragma unroll
    for (int i = 0; i < 4; i++) {
        s[i] += __shfl_xor_sync(0xffffffffu, s[i], 16);
        q[i] += __shfl_xor_sync(0xffffffffu, q[i], 16);
    }
    if (hl == 0) {
        #pragma unroll
        for (int i = 0; i < 4; i++) {
            atomicAdd(&sh[0][c4+i], s[i]);
            atomicAdd(&sh[1][c4+i], q[i]);
        }
    }
    __syncthreads();
    if (tid < 64) {
        atomicAdd(&g_sum[128+tid], (double)sh[0][tid]);
        atomicAdd(&g_ssq[128+tid], (double)sh[1][tid]);
    }
}

// ---------------------------------------------------------------------------
// a1 = relu(bn(a)) @ attn_w1^T + b1 -> g_a1 [E,8]; stats slot 3.
__global__ __launch_bounds__(256) void k_a1(const int* __restrict__ src,
        const float* __restrict__ pw2, const float* __restrict__ pb2,
        const float* __restrict__ aw1, const float* __restrict__ ab1) {
    __shared__ float sh[2][8];
    int tid = threadIdx.x, lane = tid & 31;
    int l = lane & 15, hl = lane >> 4;
    int c4 = l * 4;
    float Ar[4][3], Ab[4];
    #pragma unroll
    for (int i = 0; i < 4; i++) {
        Ar[i][0]=pw2[(c4+i)*3]; Ar[i][1]=pw2[(c4+i)*3+1]; Ar[i][2]=pw2[(c4+i)*3+2];
        Ab[i]=pb2[c4+i];
    }
    float ps0=g_scl[64],ps1=g_scl[65],ps2=g_scl[66];
    float pB0=g_bia[64],pB1=g_bia[65],pB2=g_bia[66];
    float sc[4], sb[4];
    #pragma unroll
    for (int i = 0; i < 4; i++) { sc[i]=g_scl[128+c4+i]; sb[i]=g_bia[128+c4+i]; }
    float4 w1v[8];
    #pragma unroll
    for (int j = 0; j < 8; j++) w1v[j] = *(const float4*)&aw1[j*64 + c4];
    float b1v[8];
    #pragma unroll
    for (int j = 0; j < 8; j++) b1v[j] = ab1[j];
    float st[8] = {}, sq[8] = {};
    int wId = (blockIdx.x*256 + tid) >> 5;
    int nW  = (gridDim.x*256) >> 5;
    for (int n = wId; n < NN; n += nW) {
        const float4 ad = *(const float4*)&g_adst[n*64 + c4];
        int sv = src[n*16 + l];
        #pragma unroll
        for (int jj = 0; jj < 8; jj++) {
            int ei = jj*2 + hl;
            int e  = n*16 + ei;
            int sj = __shfl_sync(0xffffffffu, sv, ei);
            float d0 = fmaxf(fmaf(g_pe[e],      ps0, pB0), 0.f);
            float d1 = fmaxf(fmaf(g_pe[EE+e],   ps1, pB1), 0.f);
            float d2 = fmaxf(fmaf(g_pe[2*EE+e], ps2, pB2), 0.f);
            const float4 as = *(const float4*)&g_asrc[sj*64 + c4];
            float a0 = as.x - ad.x + fmaf(d0,Ar[0][0],fmaf(d1,Ar[0][1],fmaf(d2,Ar[0][2],Ab[0])));
            float a1 = as.y - ad.y + fmaf(d0,Ar[1][0],fmaf(d1,Ar[1][1],fmaf(d2,Ar[1][2],Ab[1])));
            float a2 = as.z - ad.z + fmaf(d0,Ar[2][0],fmaf(d1,Ar[2][1],fmaf(d2,Ar[2][2],Ab[2])));
            float a3 = as.w - ad.w + fmaf(d0,Ar[3][0],fmaf(d1,Ar[3][1],fmaf(d2,Ar[3][2],Ab[3])));
            float r0 = fmaxf(fmaf(a0, sc[0], sb[0]), 0.f);
            float r1 = fmaxf(fmaf(a1, sc[1], sb[1]), 0.f);
            float r2 = fmaxf(fmaf(a2, sc[2], sb[2]), 0.f);
            float r3 = fmaxf(fmaf(a3, sc[3], sb[3]), 0.f);
            float p[8];
            #pragma unroll
            for (int j = 0; j < 8; j++)
                p[j] = fmaf(r0, w1v[j].x, fmaf(r1, w1v[j].y, fmaf(r2, w1v[j].z, r3 * w1v[j].w)));
            #pragma unroll
            for (int o = 8; o >= 1; o >>= 1) {
                #pragma unroll
                for (int j = 0; j < 8; j++) p[j] += __shfl_xor_sync(0xffffffffu, p[j], o);
            }
            if (l == 0) {
                float v[8];
                #pragma unroll
                for (int j = 0; j < 8; j++) { v[j] = p[j] + b1v[j]; st[j] += v[j]; sq[j] += v[j]*v[j]; }
                *(float4*)&g_a1[e*8]   = make_float4(v[0],v[1],v[2],v[3]);
                *(float4*)&g_a1[e*8+4] = make_float4(v[4],v[5],v[6],v[7]);
            }
        }
    }
    if (tid < 16) sh[tid>>3][tid&7] = 0.f;
    __syncthreads();
    #pragma unroll
    for (int j = 0; j < 8; j++) {
        st[j] += __shfl_xor_sync(0xffffffffu, st[j], 16);
        sq[j] += __shfl_xor_sync(0xffffffffu, sq[j], 16);
    }
    if (lane == 0) {
        #pragma unroll
        for (int j = 0; j < 8; j++) { atomicAdd(&sh[0][j], st[j]); atomicAdd(&sh[1][j], sq[j]); }
    }
    __syncthreads();
    if (tid < 8) {
        atomicAdd(&g_sum[192+tid], (double)sh[0][tid]);
        atomicAdd(&g_ssq[192+tid], (double)sh[1][tid]);
    }
}

// ---------------------------------------------------------------------------
// Warp-per-node: a2 from a1, softmax (16 edges), weighted aggregation; stats slot 4.
__global__ __launch_bounds__(256) void k_aggr(const int* __restrict__ src,
        const float* __restrict__ pw2, const float* __restrict__ pb2,
        const float* __restrict__ aw2, const float* __restrict__ ab2) {
    __shared__ float sh_alpha[8][16][8];
    __shared__ float sh_d[8][16][3];
    __shared__ float shS[2][64];
    int tid = threadIdx.x, lane = tid & 31, w = tid >> 5;
    int c = lane, c2 = lane + 32;
    float A0=pw2[c*3],  A1=pw2[c*3+1],  A2=pw2[c*3+2],  Abc=pb2[c];
    float B0=pw2[c2*3], B1=pw2[c2*3+1], B2=pw2[c2*3+2], Bbc=pb2[c2];
    float ps0=g_scl[64],ps1=g_scl[65],ps2=g_scl[66];
    float pB0=g_bia[64],pB1=g_bia[65],pB2=g_bia[66];
    int e = lane >> 1, j4 = (lane & 1) * 4;
    float s3[4], b3[4];
    #pragma unroll
    for (int i = 0; i < 4; i++) { s3[i]=g_scl[192+j4+i]; b3[i]=g_bia[192+j4+i]; }
    float4 w2v[8];
    #pragma unroll
    for (int j = 0; j < 8; j++) w2v[j] = *(const float4*)&aw2[j*8 + j4];
    float b2v[8];
    #pragma unroll
    for (int j = 0; j < 8; j++) b2v[j] = ab2[j];
    int j8 = lane & 7;
    float st=0, sq=0, st2=0, sq2=0;
    if (tid < 128) shS[tid>>6][tid&63] = 0.f;
    int wId = blockIdx.x*8 + w, nW = gridDim.x*8;
    for (int n = wId; n < NN; n += nW) {
        int sv = src[n*16 + (lane & 15)];
        if (lane < 16) {
            int ee = n*16 + lane;
            sh_d[w][lane][0] = fmaxf(fmaf(g_pe[ee],      ps0, pB0), 0.f);
            sh_d[w][lane][1] = fmaxf(fmaf(g_pe[EE+ee],   ps1, pB1), 0.f);
            sh_d[w][lane][2] = fmaxf(fmaf(g_pe[2*EE+ee], ps2, pB2), 0.f);
        }
        float4 bv = *(const float4*)&g_a1[n*128 + lane*4];
        float bb0 = fmaxf(fmaf(bv.x, s3[0], b3[0]), 0.f);
        float bb1 = fmaxf(fmaf(bv.y, s3[1], b3[1]), 0.f);
        float bb2 = fmaxf(fmaf(bv.z, s3[2], b3[2]), 0.f);
        float bb3 = fmaxf(fmaf(bv.w, s3[3], b3[3]), 0.f);
        float p[8];
        #pragma unroll
        for (int j = 0; j < 8; j++)
            p[j] = fmaf(bb0, w2v[j].x, fmaf(bb1, w2v[j].y, fmaf(bb2, w2v[j].z, bb3 * w2v[j].w)));
        #pragma unroll
        for (int j = 0; j < 8; j++) p[j] += __shfl_xor_sync(0xffffffffu, p[j], 1);
        if ((lane & 1) == 0) {
            #pragma unroll
            for (int j = 0; j < 8; j++) sh_alpha[w][e][j] = p[j] + b2v[j];
        }
        __syncwarp();
        if (lane < 8) {
            float mx = -1e30f;
            #pragma unroll
            for (int t = 0; t < 16; t++) mx = fmaxf(mx, sh_alpha[w][t][lane]);
            float ex[16], sm = 0.f;
            #pragma unroll
            for (int t = 0; t < 16; t++) { ex[t] = __expf(sh_alpha[w][t][lane]-mx); sm += ex[t]; }
            float inv = 1.f/sm;
            #pragma unroll
            for (int t = 0; t < 16; t++) sh_alpha[w][t][lane] = ex[t]*inv;
        }
        __syncwarp();
        float acc = 0.f, acc2 = 0.f;
        #pragma unroll
        for (int t = 0; t < 16; t++) {
            int sj = __shfl_sync(0xffffffffu, sv, t);
            float hw  = g_hW[sj*64 + c];
            float hw2 = g_hW[sj*64 + c2];
            float d0 = sh_d[w][t][0], d1 = sh_d[w][t][1], d2 = sh_d[w][t][2];
            float al = sh_alpha[w][t][j8];
            acc  = fmaf(al, hw  + fmaf(d0,A0,fmaf(d1,A1,fmaf(d2,A2,Abc))), acc);
            acc2 = fmaf(al, hw2 + fmaf(d0,B0,fmaf(d1,B1,fmaf(d2,B2,Bbc))), acc2);
        }
        g_aggr[n*64 + c]  = acc;
        g_aggr[n*64 + c2] = acc2;
        st += acc; sq += acc*acc; st2 += acc2; sq2 += acc2*acc2;
        __syncwarp();
    }
    __syncthreads();
    atomicAdd(&shS[0][c],  st);  atomicAdd(&shS[1][c],  sq);
    atomicAdd(&shS[0][c2], st2); atomicAdd(&shS[1][c2], sq2);
    __syncthreads();
    if (tid < 64) {
        atomicAdd(&g_sum[256+tid], (double)shS[0][tid]);
        atomicAdd(&g_ssq[256+tid], (double)shS[1][tid]);
    }
}

// ---------------------------------------------------------------------------
__global__ void k_final(const float* __restrict__ x, float* __restrict__ out) {
    int idx = blockIdx.x*blockDim.x + threadIdx.x;
    int c = idx & 63;
    float v = fmaf(g_t3[idx], g_scl[5*64+c], g_bia[5*64+c]) + x[idx];
    out[idx] = fmaxf(v, 0.f);
}

// ---------------------------------------------------------------------------
extern "C" void kernel_launch(void* const* d_in, const int* in_sizes, int n_in,
                              void* d_out, int out_size) {
    const float* x      = (const float*)d_in[0];
    const float* pos    = (const float*)d_in[1];
    const int*   src    = (const int*)  d_in[2];
    const float* W_in   = (const float*)d_in[3];
    const float* W_out  = (const float*)d_in[4];
    const float* pw1    = (const float*)d_in[5];
    const float* pb1    = (const float*)d_in[6];
    const float* pbn_g  = (const float*)d_in[7];
    const float* pbn_b  = (const float*)d_in[8];
    const float* pw2    = (const float*)d_in[9];
    const float* pb2    = (const float*)d_in[10];
    const float* abn1_g = (const float*)d_in[11];
    const float* abn1_b = (const float*)d_in[12];
    const float* aw1    = (const float*)d_in[13];
    const float* ab1    = (const float*)d_in[14];
    const float* abn2_g = (const float*)d_in[15];
    const float* abn2_b = (const float*)d_in[16];
    const float* aw2    = (const float*)d_in[17];
    const float* ab2    = (const float*)d_in[18];
    const float* lin_w  = (const float*)d_in[19];
    const float* lin_b  = (const float*)d_in[20];
    const float* src_w  = (const float*)d_in[21];
    const float* src_b  = (const float*)d_in[22];
    const float* dst_w  = (const float*)d_in[23];
    const float* dst_b  = (const float*)d_in[24];
    const float* bn1_g  = (const float*)d_in[25];
    const float* bn1_b  = (const float*)d_in[26];
    const float* bn2_g  = (const float*)d_in[27];
    const float* bn2_b  = (const float*)d_in[28];
    const float* bn3_g  = (const float*)d_in[29];
    const float* bn3_b  = (const float*)d_in[30];
    float* out = (float*)d_out;

    float *p_t, *p_asrc, *p_adst, *p_hW, *p_aggr, *p_t3;
    cudaGetSymbolAddress((void**)&p_t,    g_t);
    cudaGetSymbolAddress((void**)&p_asrc, g_asrc);
    cudaGetSymbolAddress((void**)&p_adst, g_adst);
    cudaGetSymbolAddress((void**)&p_hW,   g_hW);
    cudaGetSymbolAddress((void**)&p_aggr, g_aggr);
    cudaGetSymbolAddress((void**)&p_t3,   g_t3);

    k_zero<<<1,384>>>();

    // pos MLP raw outputs + posBN stats
    k_pos_stats<<<1024,256>>>(pos, src, pw1, pb1);
    k_finalize<<<1,64>>>(1, pbn_g, pbn_b, 1.0f/EE, 3);

    // t = x @ W_in^T  (+ bn1 stats)
    k_gemm<<<512,128>>>(x, W_in, nullptr, -1, 0, p_t);
    k_finalize<<<1,64>>>(0, bn1_g, bn1_b, 1.0f/NN, 64);

    // a_src/a_dst/hW = relu(bn1(t)) @ {src_w,dst_w,lin_w}^T + bias
    k_gemm<<<512,128>>>(p_t, src_w, src_b, 0, -1, p_asrc);
    k_gemm<<<512,128>>>(p_t, dst_w, dst_b, 0, -1, p_adst);
    k_gemm<<<512,128>>>(p_t, lin_w, lin_b, 0, -1, p_hW);

    // attn_bn1 stats over edges
    k_attn1_stats<<<1024,256>>>(src, pw2, pb2);
    k_finalize<<<1,64>>>(2, abn1_g, abn1_b, 1.0f/EE, 64);

    // a1 ; attn_bn2 stats
    k_a1<<<1024,256>>>(src, pw2, pb2, aw1, ab1);
    k_finalize<<<1,64>>>(3, abn2_g, abn2_b, 1.0f/EE, 8);

    // softmax + aggregation ; bn2 stats
    k_aggr<<<1024,256>>>(src, pw2, pb2, aw2, ab2);
    k_finalize<<<1,64>>>(4, bn2_g, bn2_b, 1.0f/NN, 64);

    // t3 = relu(bn2(aggr)) @ W_out^T ; bn3 stats
    k_gemm<<<512,128>>>(p_aggr, W_out, nullptr, 4, 5, p_t3);
    k_finalize<<<1,64>>>(5, bn3_g, bn3_b, 1.0f/NN, 64);

    // y = relu(bn3(t3) + x)
    k_final<<<(NN*CC)/256,256>>>(x, out);
}

// round 5
// speedup vs baseline: 1.3319x; 1.0488x over previous
#include <cuda_runtime.h>

#define NN 65536
#define KK 16
#define CC 64
#define C8 8
#define EE (NN*KK)
#define BNEPS 1e-5f

// ---- persistent scratch ----
__device__ double g_sum[6*64];
__device__ double g_ssq[6*64];
// slots: 0 bn1 | 1 posBN(3) | 2 attn_bn1 | 3 attn_bn2(8) | 4 bn2 | 5 bn3

__device__ float g_t   [NN*CC];
__device__ float g_asrc[NN*CC];
__device__ float g_adst[NN*CC];
__device__ float g_hW  [NN*CC];
__device__ float g_aggr[NN*CC];
__device__ float g_t3  [NN*CC];
__device__ float g_a1  [EE*C8];
__device__ float g_pe  [3*EE];   // planar raw pos-MLP outputs

// ---------------------------------------------------------------------------
__global__ void k_zero() {
    int i = threadIdx.x;
    if (i < 384) { g_sum[i] = 0.0; g_ssq[i] = 0.0; }
}

// ---------------------------------------------------------------------------
// 64-wide GEMM: 128 rows/block, 256 threads, 4 rows x 8 cols per thread.
// Up to 3 weight matrices share one input tile (loaded once).
// Optional pre-BN+ReLU on input (stats slot `pre`, count NN) computed in-block.
// Optional output stats into slot `stat`.
__global__ __launch_bounds__(256) void k_gemm(
        const float* __restrict__ in,
        const float* __restrict__ W0, const float* __restrict__ b0, float* __restrict__ o0,
        const float* __restrict__ W1, const float* __restrict__ b1, float* __restrict__ o1,
        const float* __restrict__ W2, const float* __restrict__ b2, float* __restrict__ o2,
        int pre, const float* __restrict__ preG, const float* __restrict__ preB,
        int stat) {
    __shared__ __align__(16) float shT[128][68];
    __shared__ __align__(16) float shW[64][68];   // quad-permuted within row
    __shared__ float shPre[2][64];
    __shared__ float shS[2][64];
    int tid = threadIdx.x;
    int row0 = blockIdx.x * 128;

    if (pre >= 0 && tid < 64) {
        double mu  = g_sum[pre*64+tid] * (1.0/NN);
        double var = g_ssq[pre*64+tid] * (1.0/NN) - mu*mu;
        float sc = preG[tid] * rsqrtf((float)var + BNEPS);
        shPre[0][tid] = sc;
        shPre[1][tid] = preB[tid] - (float)mu * sc;
    }
    if (stat >= 0 && tid < 64) { shS[0][tid] = 0.f; shS[1][tid] = 0.f; }
    __syncthreads();

    for (int idx = tid; idx < 2048; idx += 256) {
        int r = idx >> 4, i4 = (idx & 15) * 4;
        float4 v = *(const float4*)&in[(row0 + r)*64 + i4];
        if (pre >= 0) {
            v.x = fmaxf(fmaf(v.x, shPre[0][i4+0], shPre[1][i4+0]), 0.f);
            v.y = fmaxf(fmaf(v.y, shPre[0][i4+1], shPre[1][i4+1]), 0.f);
            v.z = fmaxf(fmaf(v.z, shPre[0][i4+2], shPre[1][i4+2]), 0.f);
            v.w = fmaxf(fmaf(v.w, shPre[0][i4+3], shPre[1][i4+3]), 0.f);
        }
        *(float4*)&shT[r][i4] = v;
    }

    int w = tid >> 5, lane = tid & 31;
    int g = lane >> 3, t = lane & 7;
    int rbase = w*16 + g;       // thread rows: rbase + 4*i, i=0..3
    int c0 = t * 8;             // logical cols c0..c0+7

    #pragma unroll 1
    for (int m = 0; m < 3; m++) {
        const float* W    = (m==0) ? W0 : ((m==1) ? W1 : W2);
        if (!W) break;
        const float* bias = (m==0) ? b0 : ((m==1) ? b1 : b2);
        float* out        = (m==0) ? o0 : ((m==1) ? o1 : o2);

        __syncthreads();  // shT ready (m=0) / previous compute done (m>0)
        // W[o][k] -> shW[k][perm(o)], quad q -> (q>>1)+(q&1)*8
        for (int idx = tid; idx < 4096; idx += 256) {
            int o = idx >> 6, k = idx & 63;
            int q = o >> 2;
            int po = (((q >> 1) + ((q & 1) << 3)) << 2) + (o & 3);
            shW[k][po] = W[idx];
        }
        __syncthreads();

        float acc[4][8] = {};
        #pragma unroll 4
        for (int k = 0; k < 64; k++) {
            float4 bq0 = *(float4*)&shW[k][t*4];
            float4 bq1 = *(float4*)&shW[k][32 + t*4];
            float av[4];
            #pragma unroll
            for (int i = 0; i < 4; i++) av[i] = shT[rbase + 4*i][k];
            #pragma unroll
            for (int i = 0; i < 4; i++) {
                acc[i][0] = fmaf(av[i], bq0.x, acc[i][0]);
                acc[i][1] = fmaf(av[i], bq0.y, acc[i][1]);
                acc[i][2] = fmaf(av[i], bq0.z, acc[i][2]);
                acc[i][3] = fmaf(av[i], bq0.w, acc[i][3]);
                acc[i][4] = fmaf(av[i], bq1.x, acc[i][4]);
                acc[i][5] = fmaf(av[i], bq1.y, acc[i][5]);
                acc[i][6] = fmaf(av[i], bq1.z, acc[i][6]);
                acc[i][7] = fmaf(av[i], bq1.w, acc[i][7]);
            }
        }
        float bb[8];
        #pragma unroll
        for (int j = 0; j < 8; j++) bb[j] = bias ? bias[c0+j] : 0.f;
        float s[8] = {}, q2[8] = {};
        #pragma unroll
        for (int i = 0; i < 4; i++) {
            int rr = row0 + rbase + 4*i;
            float v[8];
            #pragma unroll
            for (int j = 0; j < 8; j++) { v[j] = acc[i][j] + bb[j]; s[j] += v[j]; q2[j] += v[j]*v[j]; }
            *(float4*)&out[rr*64 + c0]     = make_float4(v[0],v[1],v[2],v[3]);
            *(float4*)&out[rr*64 + c0 + 4] = make_float4(v[4],v[5],v[6],v[7]);
        }
        if (stat >= 0) {
            #pragma unroll
            for (int j = 0; j < 8; j++) {
                s[j]  += __shfl_xor_sync(0xffffffffu, s[j], 8);
                s[j]  += __shfl_xor_sync(0xffffffffu, s[j], 16);
                q2[j] += __shfl_xor_sync(0xffffffffu, q2[j], 8);
                q2[j] += __shfl_xor_sync(0xffffffffu, q2[j], 16);
            }
            if (g == 0) {
                #pragma unroll
                for (int j = 0; j < 8; j++) {
                    atomicAdd(&shS[0][c0+j], s[j]);
                    atomicAdd(&shS[1][c0+j], q2[j]);
                }
            }
            __syncthreads();
            if (tid < 64) {
                atomicAdd(&g_sum[stat*64+tid], (double)shS[0][tid]);
                atomicAdd(&g_ssq[stat*64+tid], (double)shS[1][tid]);
            }
        }
    }
}

// ---------------------------------------------------------------------------
// pos MLP (pre-BN) raw outputs -> g_pe ; stats for posBN (slot 1)
__global__ void k_pos_stats(const float* __restrict__ pos, const int* __restrict__ src,
                            const float* __restrict__ pw1, const float* __restrict__ pb1) {
    float w00=pw1[0],w01=pw1[1],w02=pw1[2];
    float w10=pw1[3],w11=pw1[4],w12=pw1[5];
    float w20=pw1[6],w21=pw1[7],w22=pw1[8];
    float b0=pb1[0],b1=pb1[1],b2=pb1[2];
    float s0=0,s1=0,s2=0,q0=0,q1=0,q2=0;
    int stride = gridDim.x*blockDim.x;
    for (int e = blockIdx.x*blockDim.x + threadIdx.x; e < EE; e += stride) {
        int sj = src[e]; int di = e >> 4;
        float rx = pos[sj*3+0]-pos[di*3+0];
        float ry = pos[sj*3+1]-pos[di*3+1];
        float rz = pos[sj*3+2]-pos[di*3+2];
        float v0 = fmaf(rx,w00,fmaf(ry,w01,fmaf(rz,w02,b0)));
        float v1 = fmaf(rx,w10,fmaf(ry,w11,fmaf(rz,w12,b1)));
        float v2 = fmaf(rx,w20,fmaf(ry,w21,fmaf(rz,w22,b2)));
        g_pe[e] = v0; g_pe[EE+e] = v1; g_pe[2*EE+e] = v2;
        s0+=v0; q0+=v0*v0; s1+=v1; q1+=v1*v1; s2+=v2; q2+=v2*v2;
    }
    __shared__ float sh[6];
    if (threadIdx.x < 6) sh[threadIdx.x]=0.f;
    __syncthreads();
    #pragma unroll
    for (int o = 16; o; o >>= 1) {
        s0+=__shfl_xor_sync(~0u,s0,o); s1+=__shfl_xor_sync(~0u,s1,o); s2+=__shfl_xor_sync(~0u,s2,o);
        q0+=__shfl_xor_sync(~0u,q0,o); q1+=__shfl_xor_sync(~0u,q1,o); q2+=__shfl_xor_sync(~0u,q2,o);
    }
    if ((threadIdx.x & 31) == 0) {
        atomicAdd(&sh[0],s0); atomicAdd(&sh[1],s1); atomicAdd(&sh[2],s2);
        atomicAdd(&sh[3],q0); atomicAdd(&sh[4],q1); atomicAdd(&sh[5],q2);
    }
    __syncthreads();
    if (threadIdx.x < 3) {
        atomicAdd(&g_sum[64+threadIdx.x], (double)sh[threadIdx.x]);
        atomicAdd(&g_ssq[64+threadIdx.x], (double)sh[threadIdx.x+3]);
    }
}

// ---------------------------------------------------------------------------
// Computes pos BN scale/bias (slot 1) into sP[0..2]=scale, sP[3..5]=bias.
__device__ __forceinline__ void compute_pos_bn(float* sP, const float* pbnG, const float* pbnB, int tid) {
    if (tid < 3) {
        double mu  = g_sum[64+tid] * (1.0/EE);
        double var = g_ssq[64+tid] * (1.0/EE) - mu*mu;
        float sc = pbnG[tid] * rsqrtf((float)var + BNEPS);
        sP[tid] = sc; sP[3+tid] = pbnB[tid] - (float)mu*sc;
    }
}

// ---------------------------------------------------------------------------
// stats of a = a_src[src] - a_dst[dst] + delta over E (slot 2).
__global__ __launch_bounds__(256) void k_attn1_stats(const int* __restrict__ src,
        const float* __restrict__ pw2, const float* __restrict__ pb2,
        const float* __restrict__ pbnG, const float* __restrict__ pbnB) {
    __shared__ float sh[2][64];
    __shared__ float sP[6];
    int tid = threadIdx.x, lane = tid & 31;
    compute_pos_bn(sP, pbnG, pbnB, tid);
    __syncthreads();
    int l = lane & 15, hl = lane >> 4;
    int c4 = l * 4;
    float Ar[4][3], Ab[4];
    #pragma unroll
    for (int i = 0; i < 4; i++) {
        Ar[i][0]=pw2[(c4+i)*3]; Ar[i][1]=pw2[(c4+i)*3+1]; Ar[i][2]=pw2[(c4+i)*3+2];
        Ab[i]=pb2[c4+i];
    }
    float ps0=sP[0],ps1=sP[1],ps2=sP[2];
    float pB0=sP[3],pB1=sP[4],pB2=sP[5];
    float s[4]={}, q[4]={};
    int wId = (blockIdx.x*256 + tid) >> 5;
    int nW  = (gridDim.x*256) >> 5;
    for (int n = wId; n < NN; n += nW) {
        const float4 ad = *(const float4*)&g_adst[n*64 + c4];
        int sv = src[n*16 + l];
        #pragma unroll
        for (int jj = 0; jj < 8; jj++) {
            int ei = jj*2 + hl;
            int e  = n*16 + ei;
            int sj = __shfl_sync(0xffffffffu, sv, ei);
            float d0 = fmaxf(fmaf(g_pe[e],      ps0, pB0), 0.f);
            float d1 = fmaxf(fmaf(g_pe[EE+e],   ps1, pB1), 0.f);
            float d2 = fmaxf(fmaf(g_pe[2*EE+e], ps2, pB2), 0.f);
            const float4 as = *(const float4*)&g_asrc[sj*64 + c4];
            float a0 = as.x - ad.x + fmaf(d0,Ar[0][0],fmaf(d1,Ar[0][1],fmaf(d2,Ar[0][2],Ab[0])));
            float a1 = as.y - ad.y + fmaf(d0,Ar[1][0],fmaf(d1,Ar[1][1],fmaf(d2,Ar[1][2],Ab[1])));
            float a2 = as.z - ad.z + fmaf(d0,Ar[2][0],fmaf(d1,Ar[2][1],fmaf(d2,Ar[2][2],Ab[2])));
            float a3 = as.w - ad.w + fmaf(d0,Ar[3][0],fmaf(d1,Ar[3][1],fmaf(d2,Ar[3][2],Ab[3])));
            s[0]+=a0; q[0]+=a0*a0; s[1]+=a1; q[1]+=a1*a1;
            s[2]+=a2; q[2]+=a2*a2; s[3]+=a3; q[3]+=a3*a3;
        }
    }
    if (tid < 128) sh[tid>>6][tid&63] = 0.f;
    __syncthreads();
    #pragma unroll
    for (int i = 0; i < 4; i++) {
        s[i] += __shfl_xor_sync(0xffffffffu, s[i], 16);
        q[i] += __shfl_xor_sync(0xffffffffu, q[i], 16);
    }
    if (hl == 0) {
        #pragma unroll
        for (int i = 0; i < 4; i++) {
            atomicAdd(&sh[0][c4+i], s[i]);
            atomicAdd(&sh[1][c4+i], q[i]);
        }
    }
    __syncthreads();
    if (tid < 64) {
        atomicAdd(&g_sum[128+tid], (double)sh[0][tid]);
        atomicAdd(&g_ssq[128+tid], (double)sh[1][tid]);
    }
}

// ---------------------------------------------------------------------------
// a1 = relu(bn(a)) @ attn_w1^T + b1 -> g_a1 [E,8]; stats slot 3.
__global__ __launch_bounds__(256) void k_a1(const int* __restrict__ src,
        const float* __restrict__ pw2, const float* __restrict__ pb2,
        const float* __restrict__ aw1, const float* __restrict__ ab1,
        const float* __restrict__ pbnG, const float* __restrict__ pbnB,
        const float* __restrict__ a1G, const float* __restrict__ a1B) {
    __shared__ float sh[2][8];
    __shared__ float sP[6];
    __shared__ float sA[2][64];
    int tid = threadIdx.x, lane = tid & 31;
    compute_pos_bn(sP, pbnG, pbnB, tid);
    if (tid < 64) {
        double mu  = g_sum[128+tid] * (1.0/EE);
        double var = g_ssq[128+tid] * (1.0/EE) - mu*mu;
        float sc = a1G[tid] * rsqrtf((float)var + BNEPS);
        sA[0][tid] = sc; sA[1][tid] = a1B[tid] - (float)mu*sc;
    }
    __syncthreads();
    int l = lane & 15, hl = lane >> 4;
    int c4 = l * 4;
    float Ar[4][3], Ab[4];
    #pragma unroll
    for (int i = 0; i < 4; i++) {
        Ar[i][0]=pw2[(c4+i)*3]; Ar[i][1]=pw2[(c4+i)*3+1]; Ar[i][2]=pw2[(c4+i)*3+2];
        Ab[i]=pb2[c4+i];
    }
    float ps0=sP[0],ps1=sP[1],ps2=sP[2];
    float pB0=sP[3],pB1=sP[4],pB2=sP[5];
    float sc[4], sb[4];
    #pragma unroll
    for (int i = 0; i < 4; i++) { sc[i]=sA[0][c4+i]; sb[i]=sA[1][c4+i]; }
    float4 w1v[8];
    #pragma unroll
    for (int j = 0; j < 8; j++) w1v[j] = *(const float4*)&aw1[j*64 + c4];
    float b1v[8];
    #pragma unroll
    for (int j = 0; j < 8; j++) b1v[j] = ab1[j];
    float st[8] = {}, sq[8] = {};
    int wId = (blockIdx.x*256 + tid) >> 5;
    int nW  = (gridDim.x*256) >> 5;
    for (int n = wId; n < NN; n += nW) {
        const float4 ad = *(const float4*)&g_adst[n*64 + c4];
        int sv = src[n*16 + l];
        #pragma unroll
        for (int jj = 0; jj < 8; jj++) {
            int ei = jj*2 + hl;
            int e  = n*16 + ei;
            int sj = __shfl_sync(0xffffffffu, sv, ei);
            float d0 = fmaxf(fmaf(g_pe[e],      ps0, pB0), 0.f);
            float d1 = fmaxf(fmaf(g_pe[EE+e],   ps1, pB1), 0.f);
            float d2 = fmaxf(fmaf(g_pe[2*EE+e], ps2, pB2), 0.f);
            const float4 as = *(const float4*)&g_asrc[sj*64 + c4];
            float a0 = as.x - ad.x + fmaf(d0,Ar[0][0],fmaf(d1,Ar[0][1],fmaf(d2,Ar[0][2],Ab[0])));
            float a1 = as.y - ad.y + fmaf(d0,Ar[1][0],fmaf(d1,Ar[1][1],fmaf(d2,Ar[1][2],Ab[1])));
            float a2 = as.z - ad.z + fmaf(d0,Ar[2][0],fmaf(d1,Ar[2][1],fmaf(d2,Ar[2][2],Ab[2])));
            float a3 = as.w - ad.w + fmaf(d0,Ar[3][0],fmaf(d1,Ar[3][1],fmaf(d2,Ar[3][2],Ab[3])));
            float r0 = fmaxf(fmaf(a0, sc[0], sb[0]), 0.f);
            float r1 = fmaxf(fmaf(a1, sc[1], sb[1]), 0.f);
            float r2 = fmaxf(fmaf(a2, sc[2], sb[2]), 0.f);
            float r3 = fmaxf(fmaf(a3, sc[3], sb[3]), 0.f);
            float p[8];
            #pragma unroll
            for (int j = 0; j < 8; j++)
                p[j] = fmaf(r0, w1v[j].x, fmaf(r1, w1v[j].y, fmaf(r2, w1v[j].z, r3 * w1v[j].w)));
            #pragma unroll
            for (int o = 8; o >= 1; o >>= 1) {
                #pragma unroll
                for (int j = 0; j < 8; j++) p[j] += __shfl_xor_sync(0xffffffffu, p[j], o);
            }
            if (l == 0) {
                float v[8];
                #pragma unroll
                for (int j = 0; j < 8; j++) { v[j] = p[j] + b1v[j]; st[j] += v[j]; sq[j] += v[j]*v[j]; }
                *(float4*)&g_a1[e*8]   = make_float4(v[0],v[1],v[2],v[3]);
                *(float4*)&g_a1[e*8+4] = make_float4(v[4],v[5],v[6],v[7]);
            }
        }
    }
    if (tid < 16) sh[tid>>3][tid&7] = 0.f;
    __syncthreads();
    #pragma unroll
    for (int j = 0; j < 8; j++) {
        st[j] += __shfl_xor_sync(0xffffffffu, st[j], 16);
        sq[j] += __shfl_xor_sync(0xffffffffu, sq[j], 16);
    }
    if (lane == 0) {
        #pragma unroll
        for (int j = 0; j < 8; j++) { atomicAdd(&sh[0][j], st[j]); atomicAdd(&sh[1][j], sq[j]); }
    }
    __syncthreads();
    if (tid < 8) {
        atomicAdd(&g_sum[192+tid], (double)sh[0][tid]);
        atomicAdd(&g_ssq[192+tid], (double)sh[1][tid]);
    }
}

// ---------------------------------------------------------------------------
// Warp-per-node: a2 from a1, softmax (16 edges), weighted aggregation; stats slot 4.
__global__ __launch_bounds__(256) void k_aggr(const int* __restrict__ src,
        const float* __restrict__ pw2, const float* __restrict__ pb2,
        const float* __restrict__ aw2, const float* __restrict__ ab2,
        const float* __restrict__ pbnG, const float* __restrict__ pbnB,
        const float* __restrict__ a2G, const float* __restrict__ a2B) {
    __shared__ float sh_alpha[8][16][8];
    __shared__ float sh_d[8][16][3];
    __shared__ float shS[2][64];
    __shared__ float sP[6];
    __shared__ float sB[2][8];
    int tid = threadIdx.x, lane = tid & 31, w = tid >> 5;
    compute_pos_bn(sP, pbnG, pbnB, tid);
    if (tid < 8) {
        double mu  = g_sum[192+tid] * (1.0/EE);
        double var = g_ssq[192+tid] * (1.0/EE) - mu*mu;
        float sc = a2G[tid] * rsqrtf((float)var + BNEPS);
        sB[0][tid] = sc; sB[1][tid] = a2B[tid] - (float)mu*sc;
    }
    if (tid < 128) shS[tid>>6][tid&63] = 0.f;
    __syncthreads();
    int c = lane, c2 = lane + 32;
    float A0=pw2[c*3],  A1=pw2[c*3+1],  A2=pw2[c*3+2],  Abc=pb2[c];
    float B0=pw2[c2*3], B1=pw2[c2*3+1], B2=pw2[c2*3+2], Bbc=pb2[c2];
    float ps0=sP[0],ps1=sP[1],ps2=sP[2];
    float pB0=sP[3],pB1=sP[4],pB2=sP[5];
    int e = lane >> 1, j4 = (lane & 1) * 4;
    float s3[4], b3[4];
    #pragma unroll
    for (int i = 0; i < 4; i++) { s3[i]=sB[0][j4+i]; b3[i]=sB[1][j4+i]; }
    float4 w2v[8];
    #pragma unroll
    for (int j = 0; j < 8; j++) w2v[j] = *(const float4*)&aw2[j*8 + j4];
    float b2v[8];
    #pragma unroll
    for (int j = 0; j < 8; j++) b2v[j] = ab2[j];
    int j8 = lane & 7;
    float st=0, sq=0, st2=0, sq2=0;
    int wId = blockIdx.x*8 + w, nW = gridDim.x*8;
    for (int n = wId; n < NN; n += nW) {
        int sv = src[n*16 + (lane & 15)];
        if (lane < 16) {
            int ee = n*16 + lane;
            sh_d[w][lane][0] = fmaxf(fmaf(g_pe[ee],      ps0, pB0), 0.f);
            sh_d[w][lane][1] = fmaxf(fmaf(g_pe[EE+ee],   ps1, pB1), 0.f);
            sh_d[w][lane][2] = fmaxf(fmaf(g_pe[2*EE+ee], ps2, pB2), 0.f);
        }
        float4 bv = *(const float4*)&g_a1[n*128 + lane*4];
        float bb0 = fmaxf(fmaf(bv.x, s3[0], b3[0]), 0.f);
        float bb1 = fmaxf(fmaf(bv.y, s3[1], b3[1]), 0.f);
        float bb2 = fmaxf(fmaf(bv.z, s3[2], b3[2]), 0.f);
        float bb3 = fmaxf(fmaf(bv.w, s3[3], b3[3]), 0.f);
        float p[8];
        #pragma unroll
        for (int j = 0; j < 8; j++)
            p[j] = fmaf(bb0, w2v[j].x, fmaf(bb1, w2v[j].y, fmaf(bb2, w2v[j].z, bb3 * w2v[j].w)));
        #pragma unroll
        for (int j = 0; j < 8; j++) p[j] += __shfl_xor_sync(0xffffffffu, p[j], 1);
        if ((lane & 1) == 0) {
            #pragma unroll
            for (int j = 0; j < 8; j++) sh_alpha[w][e][j] = p[j] + b2v[j];
        }
        __syncwarp();
        if (lane < 8) {
            float mx = -1e30f;
            #pragma unroll
            for (int t = 0; t < 16; t++) mx = fmaxf(mx, sh_alpha[w][t][lane]);
            float ex[16], sm = 0.f;
            #pragma unroll
            for (int t = 0; t < 16; t++) { ex[t] = __expf(sh_alpha[w][t][lane]-mx); sm += ex[t]; }
            float inv = 1.f/sm;
            #pragma unroll
            for (int t = 0; t < 16; t++) sh_alpha[w][t][lane] = ex[t]*inv;
        }
        __syncwarp();
        float acc = 0.f, acc2 = 0.f;
        #pragma unroll
        for (int t = 0; t < 16; t++) {
            int sj = __shfl_sync(0xffffffffu, sv, t);
            float hw  = g_hW[sj*64 + c];
            float hw2 = g_hW[sj*64 + c2];
            float d0 = sh_d[w][t][0], d1 = sh_d[w][t][1], d2 = sh_d[w][t][2];
            float al = sh_alpha[w][t][j8];
            acc  = fmaf(al, hw  + fmaf(d0,A0,fmaf(d1,A1,fmaf(d2,A2,Abc))), acc);
            acc2 = fmaf(al, hw2 + fmaf(d0,B0,fmaf(d1,B1,fmaf(d2,B2,Bbc))), acc2);
        }
        g_aggr[n*64 + c]  = acc;
        g_aggr[n*64 + c2] = acc2;
        st += acc; sq += acc*acc; st2 += acc2; sq2 += acc2*acc2;
        __syncwarp();
    }
    __syncthreads();
    atomicAdd(&shS[0][c],  st);  atomicAdd(&shS[1][c],  sq);
    atomicAdd(&shS[0][c2], st2); atomicAdd(&shS[1][c2], sq2);
    __syncthreads();
    if (tid < 64) {
        atomicAdd(&g_sum[256+tid], (double)shS[0][tid]);
        atomicAdd(&g_ssq[256+tid], (double)shS[1][tid]);
    }
}

// ---------------------------------------------------------------------------
__global__ __launch_bounds__(256) void k_final(const float* __restrict__ x,
        const float* __restrict__ g, const float* __restrict__ b,
        float* __restrict__ out) {
    __shared__ float sSc[64], sBi[64];
    int tid = threadIdx.x;
    if (tid < 64) {
        double mu  = g_sum[5*64+tid] * (1.0/NN);
        double var = g_ssq[5*64+tid] * (1.0/NN) - mu*mu;
        float sc = g[tid] * rsqrtf((float)var + BNEPS);
        sSc[tid] = sc; sBi[tid] = b[tid] - (float)mu*sc;
    }
    __syncthreads();
    int stride = gridDim.x * blockDim.x;
    for (int i4 = blockIdx.x*blockDim.x + tid; i4 < NN*16; i4 += stride) {
        float4 v  = *(const float4*)&g_t3[i4*4];
        float4 xv = *(const float4*)&x[i4*4];
        int cg = (i4 & 15) * 4;
        float4 r;
        r.x = fmaxf(fmaf(v.x, sSc[cg+0], sBi[cg+0]) + xv.x, 0.f);
        r.y = fmaxf(fmaf(v.y, sSc[cg+1], sBi[cg+1]) + xv.y, 0.f);
        r.z = fmaxf(fmaf(v.z, sSc[cg+2], sBi[cg+2]) + xv.z, 0.f);
        r.w = fmaxf(fmaf(v.w, sSc[cg+3], sBi[cg+3]) + xv.w, 0.f);
        *(float4*)&out[i4*4] = r;
    }
}

// ---------------------------------------------------------------------------
extern "C" void kernel_launch(void* const* d_in, const int* in_sizes, int n_in,
                              void* d_out, int out_size) {
    const float* x      = (const float*)d_in[0];
    const float* pos    = (const float*)d_in[1];
    const int*   src    = (const int*)  d_in[2];
    const float* W_in   = (const float*)d_in[3];
    const float* W_out  = (const float*)d_in[4];
    const float* pw1    = (const float*)d_in[5];
    const float* pb1    = (const float*)d_in[6];
    const float* pbn_g  = (const float*)d_in[7];
    const float* pbn_b  = (const float*)d_in[8];
    const float* pw2    = (const float*)d_in[9];
    const float* pb2    = (const float*)d_in[10];
    const float* abn1_g = (const float*)d_in[11];
    const float* abn1_b = (const float*)d_in[12];
    const float* aw1    = (const float*)d_in[13];
    const float* ab1    = (const float*)d_in[14];
    const float* abn2_g = (const float*)d_in[15];
    const float* abn2_b = (const float*)d_in[16];
    const float* aw2    = (const float*)d_in[17];
    const float* ab2    = (const float*)d_in[18];
    const float* lin_w  = (const float*)d_in[19];
    const float* lin_b  = (const float*)d_in[20];
    const float* src_w  = (const float*)d_in[21];
    const float* src_b  = (const float*)d_in[22];
    const float* dst_w  = (const float*)d_in[23];
    const float* dst_b  = (const float*)d_in[24];
    const float* bn1_g  = (const float*)d_in[25];
    const float* bn1_b  = (const float*)d_in[26];
    const float* bn2_g  = (const float*)d_in[27];
    const float* bn2_b  = (const float*)d_in[28];
    const float* bn3_g  = (const float*)d_in[29];
    const float* bn3_b  = (const float*)d_in[30];
    float* out = (float*)d_out;

    float *p_t, *p_asrc, *p_adst, *p_hW, *p_aggr, *p_t3;
    cudaGetSymbolAddress((void**)&p_t,    g_t);
    cudaGetSymbolAddress((void**)&p_asrc, g_asrc);
    cudaGetSymbolAddress((void**)&p_adst, g_adst);
    cudaGetSymbolAddress((void**)&p_hW,   g_hW);
    cudaGetSymbolAddress((void**)&p_aggr, g_aggr);
    cudaGetSymbolAddress((void**)&p_t3,   g_t3);

    k_zero<<<1,384>>>();

    // pos MLP raw outputs + posBN stats
    k_pos_stats<<<1024,256>>>(pos, src, pw1, pb1);

    // t = x @ W_in^T (+ bn1 stats)
    k_gemm<<<512,256>>>(x, W_in, nullptr, p_t,
                        nullptr, nullptr, nullptr, nullptr, nullptr, nullptr,
                        -1, nullptr, nullptr, 0);

    // a_src/a_dst/hW = relu(bn1(t)) @ {src_w,dst_w,lin_w}^T + bias (fused triple)
    k_gemm<<<512,256>>>(p_t, src_w, src_b, p_asrc,
                        dst_w, dst_b, p_adst,
                        lin_w, lin_b, p_hW,
                        0, bn1_g, bn1_b, -1);

    // attn_bn1 stats over edges
    k_attn1_stats<<<1024,256>>>(src, pw2, pb2, pbn_g, pbn_b);

    // a1 ; attn_bn2 stats
    k_a1<<<1024,256>>>(src, pw2, pb2, aw1, ab1, pbn_g, pbn_b, abn1_g, abn1_b);

    // softmax + aggregation ; bn2 stats
    k_aggr<<<1024,256>>>(src, pw2, pb2, aw2, ab2, pbn_g, pbn_b, abn2_g, abn2_b);

    // t3 = relu(bn2(aggr)) @ W_out^T ; bn3 stats
    k_gemm<<<512,256>>>(p_aggr, W_out, nullptr, p_t3,
                        nullptr, nullptr, nullptr, nullptr, nullptr, nullptr,
                        4, bn2_g, bn2_b, 5);

    // y = relu(bn3(t3) + x)
    k_final<<<1024,256>>>(x, bn3_g, bn3_b, out);
}

// round 6
// speedup vs baseline: 1.5219x; 1.1427x over previous
#include <cuda_runtime.h>

#define NN 65536
#define KK 16
#define CC 64
#define C8 8
#define EE (NN*KK)
#define BNEPS 1e-5f

typedef unsigned long long u64;
__device__ __forceinline__ u64 pk2(float lo, float hi) {
    u64 r; asm("mov.b64 %0, {%1,%2};" : "=l"(r) : "f"(lo), "f"(hi)); return r;
}
__device__ __forceinline__ void up2(u64 v, float& a, float& b) {
    asm("mov.b64 {%0,%1}, %2;" : "=f"(a), "=f"(b) : "l"(v));
}
__device__ __forceinline__ u64 f2(u64 a, u64 b, u64 c) {
    u64 d; asm("fma.rn.f32x2 %0, %1, %2, %3;" : "=l"(d) : "l"(a), "l"(b), "l"(c)); return d;
}
__device__ __forceinline__ u64 ad2(u64 x, u64 y) {
    u64 d; asm("add.rn.f32x2 %0, %1, %2;" : "=l"(d) : "l"(x), "l"(y)); return d;
}
#define SIGN2 0x8000000080000000ull

// ---- persistent scratch ----
__device__ double g_sum[6*64];
__device__ double g_ssq[6*64];
// slots: 0 bn1 | 1 posBN(3) | 2 attn_bn1 | 3 attn_bn2(8) | 4 bn2 | 5 bn3

__device__ float g_t   [NN*CC];
__device__ float g_asrc[NN*CC];
__device__ float g_adst[NN*CC];
__device__ float g_hW  [NN*CC];
__device__ float g_aggr[NN*CC];
__device__ float g_t3  [NN*CC];
__device__ float g_a1  [EE*C8];
__device__ float g_pe  [3*EE];   // planar raw pos-MLP outputs

// ---------------------------------------------------------------------------
__global__ void k_zero() {
    int i = threadIdx.x;
    if (i < 384) { g_sum[i] = 0.0; g_ssq[i] = 0.0; }
}

// ---------------------------------------------------------------------------
// 64-wide GEMM: 128 rows/block, 256 threads, 4 rows x 8 cols per thread.
// FFMA2 inner loop. Up to 3 weight matrices share one input tile.
__global__ __launch_bounds__(256) void k_gemm(
        const float* __restrict__ in,
        const float* __restrict__ W0, const float* __restrict__ b0, float* __restrict__ o0,
        const float* __restrict__ W1, const float* __restrict__ b1, float* __restrict__ o1,
        const float* __restrict__ W2, const float* __restrict__ b2, float* __restrict__ o2,
        int pre, const float* __restrict__ preG, const float* __restrict__ preB,
        int stat) {
    __shared__ __align__(16) float shT[128][68];
    __shared__ __align__(16) float shW[64][68];   // quad-permuted within row
    __shared__ float shPre[2][64];
    __shared__ float shS[2][64];
    int tid = threadIdx.x;
    int row0 = blockIdx.x * 128;

    if (pre >= 0 && tid < 64) {
        double mu  = g_sum[pre*64+tid] * (1.0/NN);
        double var = g_ssq[pre*64+tid] * (1.0/NN) - mu*mu;
        float sc = preG[tid] * rsqrtf((float)var + BNEPS);
        shPre[0][tid] = sc;
        shPre[1][tid] = preB[tid] - (float)mu * sc;
    }
    if (stat >= 0 && tid < 64) { shS[0][tid] = 0.f; shS[1][tid] = 0.f; }
    __syncthreads();

    for (int idx = tid; idx < 2048; idx += 256) {
        int r = idx >> 4, i4 = (idx & 15) * 4;
        float4 v = *(const float4*)&in[(row0 + r)*64 + i4];
        if (pre >= 0) {
            v.x = fmaxf(fmaf(v.x, shPre[0][i4+0], shPre[1][i4+0]), 0.f);
            v.y = fmaxf(fmaf(v.y, shPre[0][i4+1], shPre[1][i4+1]), 0.f);
            v.z = fmaxf(fmaf(v.z, shPre[0][i4+2], shPre[1][i4+2]), 0.f);
            v.w = fmaxf(fmaf(v.w, shPre[0][i4+3], shPre[1][i4+3]), 0.f);
        }
        *(float4*)&shT[r][i4] = v;
    }

    int w = tid >> 5, lane = tid & 31;
    int g = lane >> 3, t = lane & 7;
    int rbase = w*16 + g;       // thread rows: rbase + 4*i, i=0..3
    int c0 = t * 8;             // logical cols c0..c0+7

    #pragma unroll 1
    for (int m = 0; m < 3; m++) {
        const float* W    = (m==0) ? W0 : ((m==1) ? W1 : W2);
        if (!W) break;
        const float* bias = (m==0) ? b0 : ((m==1) ? b1 : b2);
        float* out        = (m==0) ? o0 : ((m==1) ? o1 : o2);

        __syncthreads();
        for (int idx = tid; idx < 4096; idx += 256) {
            int o = idx >> 6, k = idx & 63;
            int q = o >> 2;
            int po = (((q >> 1) + ((q & 1) << 3)) << 2) + (o & 3);
            shW[k][po] = W[idx];
        }
        __syncthreads();

        u64 acc2[4][4] = {};
        #pragma unroll 4
        for (int k = 0; k < 64; k++) {
            ulonglong2 B0 = *(const ulonglong2*)&shW[k][t*4];
            ulonglong2 B1 = *(const ulonglong2*)&shW[k][32 + t*4];
            #pragma unroll
            for (int i = 0; i < 4; i++) {
                float av = shT[rbase + 4*i][k];
                u64 av2 = pk2(av, av);
                acc2[i][0] = f2(av2, B0.x, acc2[i][0]);
                acc2[i][1] = f2(av2, B0.y, acc2[i][1]);
                acc2[i][2] = f2(av2, B1.x, acc2[i][2]);
                acc2[i][3] = f2(av2, B1.y, acc2[i][3]);
            }
        }
        float bb[8];
        #pragma unroll
        for (int j = 0; j < 8; j++) bb[j] = bias ? bias[c0+j] : 0.f;
        float s[8] = {}, q2[8] = {};
        #pragma unroll
        for (int i = 0; i < 4; i++) {
            int rr = row0 + rbase + 4*i;
            float v[8];
            up2(acc2[i][0], v[0], v[1]);
            up2(acc2[i][1], v[2], v[3]);
            up2(acc2[i][2], v[4], v[5]);
            up2(acc2[i][3], v[6], v[7]);
            #pragma unroll
            for (int j = 0; j < 8; j++) { v[j] += bb[j]; s[j] += v[j]; q2[j] += v[j]*v[j]; }
            *(float4*)&out[rr*64 + c0]     = make_float4(v[0],v[1],v[2],v[3]);
            *(float4*)&out[rr*64 + c0 + 4] = make_float4(v[4],v[5],v[6],v[7]);
        }
        if (stat >= 0) {
            #pragma unroll
            for (int j = 0; j < 8; j++) {
                s[j]  += __shfl_xor_sync(0xffffffffu, s[j], 8);
                s[j]  += __shfl_xor_sync(0xffffffffu, s[j], 16);
                q2[j] += __shfl_xor_sync(0xffffffffu, q2[j], 8);
                q2[j] += __shfl_xor_sync(0xffffffffu, q2[j], 16);
            }
            if (g == 0) {
                #pragma unroll
                for (int j = 0; j < 8; j++) {
                    atomicAdd(&shS[0][c0+j], s[j]);
                    atomicAdd(&shS[1][c0+j], q2[j]);
                }
            }
            __syncthreads();
            if (tid < 64) {
                atomicAdd(&g_sum[stat*64+tid], (double)shS[0][tid]);
                atomicAdd(&g_ssq[stat*64+tid], (double)shS[1][tid]);
            }
        }
    }
}

// ---------------------------------------------------------------------------
// pos MLP (pre-BN) raw outputs -> g_pe ; stats for posBN (slot 1)
__global__ void k_pos_stats(const float* __restrict__ pos, const int* __restrict__ src,
                            const float* __restrict__ pw1, const float* __restrict__ pb1) {
    float w00=pw1[0],w01=pw1[1],w02=pw1[2];
    float w10=pw1[3],w11=pw1[4],w12=pw1[5];
    float w20=pw1[6],w21=pw1[7],w22=pw1[8];
    float b0=pb1[0],b1=pb1[1],b2=pb1[2];
    float s0=0,s1=0,s2=0,q0=0,q1=0,q2=0;
    int stride = gridDim.x*blockDim.x;
    for (int e = blockIdx.x*blockDim.x + threadIdx.x; e < EE; e += stride) {
        int sj = src[e]; int di = e >> 4;
        float rx = pos[sj*3+0]-pos[di*3+0];
        float ry = pos[sj*3+1]-pos[di*3+1];
        float rz = pos[sj*3+2]-pos[di*3+2];
        float v0 = fmaf(rx,w00,fmaf(ry,w01,fmaf(rz,w02,b0)));
        float v1 = fmaf(rx,w10,fmaf(ry,w11,fmaf(rz,w12,b1)));
        float v2 = fmaf(rx,w20,fmaf(ry,w21,fmaf(rz,w22,b2)));
        g_pe[e] = v0; g_pe[EE+e] = v1; g_pe[2*EE+e] = v2;
        s0+=v0; q0+=v0*v0; s1+=v1; q1+=v1*v1; s2+=v2; q2+=v2*v2;
    }
    __shared__ float sh[6];
    if (threadIdx.x < 6) sh[threadIdx.x]=0.f;
    __syncthreads();
    #pragma unroll
    for (int o = 16; o; o >>= 1) {
        s0+=__shfl_xor_sync(~0u,s0,o); s1+=__shfl_xor_sync(~0u,s1,o); s2+=__shfl_xor_sync(~0u,s2,o);
        q0+=__shfl_xor_sync(~0u,q0,o); q1+=__shfl_xor_sync(~0u,q1,o); q2+=__shfl_xor_sync(~0u,q2,o);
    }
    if ((threadIdx.x & 31) == 0) {
        atomicAdd(&sh[0],s0); atomicAdd(&sh[1],s1); atomicAdd(&sh[2],s2);
        atomicAdd(&sh[3],q0); atomicAdd(&sh[4],q1); atomicAdd(&sh[5],q2);
    }
    __syncthreads();
    if (threadIdx.x < 3) {
        atomicAdd(&g_sum[64+threadIdx.x], (double)sh[threadIdx.x]);
        atomicAdd(&g_ssq[64+threadIdx.x], (double)sh[threadIdx.x+3]);
    }
}

// ---------------------------------------------------------------------------
__device__ __forceinline__ void compute_pos_bn(float* sP, const float* pbnG, const float* pbnB, int tid) {
    if (tid < 3) {
        double mu  = g_sum[64+tid] * (1.0/EE);
        double var = g_ssq[64+tid] * (1.0/EE) - mu*mu;
        float sc = pbnG[tid] * rsqrtf((float)var + BNEPS);
        sP[tid] = sc; sP[3+tid] = pbnB[tid] - (float)mu*sc;
    }
}

// ---------------------------------------------------------------------------
// stats of a = a_src[src] - a_dst[dst] + delta over E (slot 2). f32x2 math.
__global__ __launch_bounds__(256) void k_attn1_stats(const int* __restrict__ src,
        const float* __restrict__ pw2, const float* __restrict__ pb2,
        const float* __restrict__ pbnG, const float* __restrict__ pbnB) {
    __shared__ float sh[2][64];
    __shared__ float sP[6];
    int tid = threadIdx.x, lane = tid & 31;
    compute_pos_bn(sP, pbnG, pbnB, tid);
    __syncthreads();
    int l = lane & 15, hl = lane >> 4;
    int c4 = l * 4;
    u64 PA[3], PB[3];
    #pragma unroll
    for (int k = 0; k < 3; k++) {
        PA[k] = pk2(pw2[(c4+0)*3+k], pw2[(c4+1)*3+k]);
        PB[k] = pk2(pw2[(c4+2)*3+k], pw2[(c4+3)*3+k]);
    }
    u64 Ab01 = pk2(pb2[c4+0], pb2[c4+1]);
    u64 Ab23 = pk2(pb2[c4+2], pb2[c4+3]);
    float ps0=sP[0],ps1=sP[1],ps2=sP[2];
    float pB0=sP[3],pB1=sP[4],pB2=sP[5];
    u64 s01=0, s23=0, q01=0, q23=0;
    int wId = (blockIdx.x*256 + tid) >> 5;
    int nW  = (gridDim.x*256) >> 5;
    for (int n = wId; n < NN; n += nW) {
        ulonglong2 adv = *(const ulonglong2*)&g_adst[n*64 + c4];
        u64 AbAd01 = ad2(Ab01, adv.x ^ SIGN2);
        u64 AbAd23 = ad2(Ab23, adv.y ^ SIGN2);
        int sv = src[n*16 + l];
        #pragma unroll
        for (int jj = 0; jj < 8; jj++) {
            int ei = jj*2 + hl;
            int e  = n*16 + ei;
            int sj = __shfl_sync(0xffffffffu, sv, ei);
            float d0 = fmaxf(fmaf(g_pe[e],      ps0, pB0), 0.f);
            float d1 = fmaxf(fmaf(g_pe[EE+e],   ps1, pB1), 0.f);
            float d2 = fmaxf(fmaf(g_pe[2*EE+e], ps2, pB2), 0.f);
            u64 D0 = pk2(d0,d0), D1 = pk2(d1,d1), D2 = pk2(d2,d2);
            ulonglong2 asv = *(const ulonglong2*)&g_asrc[sj*64 + c4];
            u64 a01 = ad2(asv.x, f2(D0,PA[0], f2(D1,PA[1], f2(D2,PA[2], AbAd01))));
            u64 a23 = ad2(asv.y, f2(D0,PB[0], f2(D1,PB[1], f2(D2,PB[2], AbAd23))));
            s01 = ad2(s01, a01); q01 = f2(a01, a01, q01);
            s23 = ad2(s23, a23); q23 = f2(a23, a23, q23);
        }
    }
    float s[4], q[4];
    up2(s01, s[0], s[1]); up2(s23, s[2], s[3]);
    up2(q01, q[0], q[1]); up2(q23, q[2], q[3]);
    if (tid < 128) sh[tid>>6][tid&63] = 0.f;
    __syncthreads();
    #pragma unroll
    for (int i = 0; i < 4; i++) {
        s[i] += __shfl_xor_sync(0xffffffffu, s[i], 16);
        q[i] += __shfl_xor_sync(0xffffffffu, q[i], 16);
    }
    if (hl == 0) {
        #pragma unroll
        for (int i = 0; i < 4; i++) {
            atomicAdd(&sh[0][c4+i], s[i]);
            atomicAdd(&sh[1][c4+i], q[i]);
        }
    }
    __syncthreads();
    if (tid < 64) {
        atomicAdd(&g_sum[128+tid], (double)sh[0][tid]);
        atomicAdd(&g_ssq[128+tid], (double)sh[1][tid]);
    }
}

// ---------------------------------------------------------------------------
// a1 = relu(bn(a)) @ attn_w1^T + b1 -> g_a1 [E,8]; stats slot 3.
// f32x2 channel math + FFMA2 projection + value-halving reduction (8 shfl/edge).
__global__ __launch_bounds__(256) void k_a1(const int* __restrict__ src,
        const float* __restrict__ pw2, const float* __restrict__ pb2,
        const float* __restrict__ aw1, const float* __restrict__ ab1,
        const float* __restrict__ pbnG, const float* __restrict__ pbnB,
        const float* __restrict__ a1G, const float* __restrict__ a1B) {
    __shared__ float shQ[2][8];
    __shared__ float sP[6];
    __shared__ float sA[2][64];
    int tid = threadIdx.x, lane = tid & 31;
    compute_pos_bn(sP, pbnG, pbnB, tid);
    if (tid < 64) {
        double mu  = g_sum[128+tid] * (1.0/EE);
        double var = g_ssq[128+tid] * (1.0/EE) - mu*mu;
        float sc = a1G[tid] * rsqrtf((float)var + BNEPS);
        sA[0][tid] = sc; sA[1][tid] = a1B[tid] - (float)mu*sc;
    }
    __syncthreads();
    int l = lane & 15, hl = lane >> 4;
    int c4 = l * 4;
    u64 PA[3], PB[3];
    #pragma unroll
    for (int k = 0; k < 3; k++) {
        PA[k] = pk2(pw2[(c4+0)*3+k], pw2[(c4+1)*3+k]);
        PB[k] = pk2(pw2[(c4+2)*3+k], pw2[(c4+3)*3+k]);
    }
    u64 Ab01 = pk2(pb2[c4+0], pb2[c4+1]);
    u64 Ab23 = pk2(pb2[c4+2], pb2[c4+3]);
    float ps0=sP[0],ps1=sP[1],ps2=sP[2];
    float pB0=sP[3],pB1=sP[4],pB2=sP[5];
    float sc[4], sb[4];
    #pragma unroll
    for (int i = 0; i < 4; i++) { sc[i]=sA[0][c4+i]; sb[i]=sA[1][c4+i]; }
    // WT[c][jp] = (aw1[2jp][c4+c], aw1[2jp+1][c4+c])
    u64 WT[4][4];
    #pragma unroll
    for (int jp = 0; jp < 4; jp++)
        #pragma unroll
        for (int c = 0; c < 4; c++)
            WT[c][jp] = pk2(aw1[(2*jp)*64 + c4 + c], aw1[(2*jp+1)*64 + c4 + c]);
    int jown = l >> 1;
    float bj = ab1[jown];
    float st = 0.f, sq = 0.f;
    int wId = (blockIdx.x*256 + tid) >> 5;
    int nW  = (gridDim.x*256) >> 5;
    for (int n = wId; n < NN; n += nW) {
        ulonglong2 adv = *(const ulonglong2*)&g_adst[n*64 + c4];
        u64 AbAd01 = ad2(Ab01, adv.x ^ SIGN2);
        u64 AbAd23 = ad2(Ab23, adv.y ^ SIGN2);
        int sv = src[n*16 + l];
        #pragma unroll
        for (int jj = 0; jj < 8; jj++) {
            int ei = jj*2 + hl;
            int e  = n*16 + ei;
            int sj = __shfl_sync(0xffffffffu, sv, ei);
            float d0 = fmaxf(fmaf(g_pe[e],      ps0, pB0), 0.f);
            float d1 = fmaxf(fmaf(g_pe[EE+e],   ps1, pB1), 0.f);
            float d2 = fmaxf(fmaf(g_pe[2*EE+e], ps2, pB2), 0.f);
            u64 D0 = pk2(d0,d0), D1 = pk2(d1,d1), D2 = pk2(d2,d2);
            ulonglong2 asv = *(const ulonglong2*)&g_asrc[sj*64 + c4];
            u64 a01 = ad2(asv.x, f2(D0,PA[0], f2(D1,PA[1], f2(D2,PA[2], AbAd01))));
            u64 a23 = ad2(asv.y, f2(D0,PB[0], f2(D1,PB[1], f2(D2,PB[2], AbAd23))));
            float aa0, aa1, aa2, aa3;
            up2(a01, aa0, aa1); up2(a23, aa2, aa3);
            float r0 = fmaxf(fmaf(aa0, sc[0], sb[0]), 0.f);
            float r1 = fmaxf(fmaf(aa1, sc[1], sb[1]), 0.f);
            float r2 = fmaxf(fmaf(aa2, sc[2], sb[2]), 0.f);
            float r3 = fmaxf(fmaf(aa3, sc[3], sb[3]), 0.f);
            u64 R0 = pk2(r0,r0), R1 = pk2(r1,r1), R2 = pk2(r2,r2), R3 = pk2(r3,r3);
            float p[8];
            #pragma unroll
            for (int jp = 0; jp < 4; jp++) {
                u64 t2 = f2(R0, WT[0][jp], f2(R1, WT[1][jp], f2(R2, WT[2][jp], f2(R3, WT[3][jp], 0ull))));
                up2(t2, p[2*jp], p[2*jp+1]);
            }
            // value-halving reduction over 16 lanes (8 shfl)
            #pragma unroll
            for (int j = 0; j < 4; j++) {
                float v = (l & 8) ? p[j] : p[j+4];
                float ww = __shfl_xor_sync(0xffffffffu, v, 8);
                p[j] = ((l & 8) ? p[j+4] : p[j]) + ww;
            }
            #pragma unroll
            for (int j = 0; j < 2; j++) {
                float v = (l & 4) ? p[j] : p[j+2];
                float ww = __shfl_xor_sync(0xffffffffu, v, 4);
                p[j] = ((l & 4) ? p[j+2] : p[j]) + ww;
            }
            {
                float v = (l & 2) ? p[0] : p[1];
                float ww = __shfl_xor_sync(0xffffffffu, v, 2);
                p[0] = ((l & 2) ? p[1] : p[0]) + ww;
            }
            p[0] += __shfl_xor_sync(0xffffffffu, p[0], 1);
            float vv = p[0] + bj;
            if ((l & 1) == 0) {
                g_a1[e*8 + jown] = vv;
                st += vv; sq += vv*vv;
            }
        }
    }
    if (tid < 16) shQ[tid>>3][tid&7] = 0.f;
    __syncthreads();
    if ((l & 1) == 0) { atomicAdd(&shQ[0][jown], st); atomicAdd(&shQ[1][jown], sq); }
    __syncthreads();
    if (tid < 8) {
        atomicAdd(&g_sum[192+tid], (double)shQ[0][tid]);
        atomicAdd(&g_ssq[192+tid], (double)shQ[1][tid]);
    }
}

// ---------------------------------------------------------------------------
// Warp-per-node: a2 from a1, softmax (16 edges), weighted aggregation; stats slot 4.
__global__ __launch_bounds__(256) void k_aggr(const int* __restrict__ src,
        const float* __restrict__ pw2, const float* __restrict__ pb2,
        const float* __restrict__ aw2, const float* __restrict__ ab2,
        const float* __restrict__ pbnG, const float* __restrict__ pbnB,
        const float* __restrict__ a2G, const float* __restrict__ a2B) {
    __shared__ float sh_alpha[8][16][8];
    __shared__ float sh_d[8][16][3];
    __shared__ float shS[2][64];
    __shared__ float sP[6];
    __shared__ float sB[2][8];
    int tid = threadIdx.x, lane = tid & 31, w = tid >> 5;
    compute_pos_bn(sP, pbnG, pbnB, tid);
    if (tid < 8) {
        double mu  = g_sum[192+tid] * (1.0/EE);
        double var = g_ssq[192+tid] * (1.0/EE) - mu*mu;
        float sc = a2G[tid] * rsqrtf((float)var + BNEPS);
        sB[0][tid] = sc; sB[1][tid] = a2B[tid] - (float)mu*sc;
    }
    if (tid < 128) shS[tid>>6][tid&63] = 0.f;
    __syncthreads();
    int c = lane, c2 = lane + 32;
    float A0=pw2[c*3],  A1=pw2[c*3+1],  A2=pw2[c*3+2],  Abc=pb2[c];
    float B0=pw2[c2*3], B1=pw2[c2*3+1], B2=pw2[c2*3+2], Bbc=pb2[c2];
    float ps0=sP[0],ps1=sP[1],ps2=sP[2];
    float pB0=sP[3],pB1=sP[4],pB2=sP[5];
    int e = lane >> 1, j4 = (lane & 1) * 4;
    float s3[4], b3[4];
    #pragma unroll
    for (int i = 0; i < 4; i++) { s3[i]=sB[0][j4+i]; b3[i]=sB[1][j4+i]; }
    float4 w2v[8];
    #pragma unroll
    for (int j = 0; j < 8; j++) w2v[j] = *(const float4*)&aw2[j*8 + j4];
    float b2v[8];
    #pragma unroll
    for (int j = 0; j < 8; j++) b2v[j] = ab2[j];
    int j8 = lane & 7;
    float st=0, sq=0, st2=0, sq2=0;
    int wId = blockIdx.x*8 + w, nW = gridDim.x*8;
    for (int n = wId; n < NN; n += nW) {
        int sv = src[n*16 + (lane & 15)];
        if (lane < 16) {
            int ee = n*16 + lane;
            sh_d[w][lane][0] = fmaxf(fmaf(g_pe[ee],      ps0, pB0), 0.f);
            sh_d[w][lane][1] = fmaxf(fmaf(g_pe[EE+ee],   ps1, pB1), 0.f);
            sh_d[w][lane][2] = fmaxf(fmaf(g_pe[2*EE+ee], ps2, pB2), 0.f);
        }
        float4 bv = *(const float4*)&g_a1[n*128 + lane*4];
        float bb0 = fmaxf(fmaf(bv.x, s3[0], b3[0]), 0.f);
        float bb1 = fmaxf(fmaf(bv.y, s3[1], b3[1]), 0.f);
        float bb2 = fmaxf(fmaf(bv.z, s3[2], b3[2]), 0.f);
        float bb3 = fmaxf(fmaf(bv.w, s3[3], b3[3]), 0.f);
        float p[8];
        #pragma unroll
        for (int j = 0; j < 8; j++)
            p[j] = fmaf(bb0, w2v[j].x, fmaf(bb1, w2v[j].y, fmaf(bb2, w2v[j].z, bb3 * w2v[j].w)));
        #pragma unroll
        for (int j = 0; j < 8; j++) p[j] += __shfl_xor_sync(0xffffffffu, p[j], 1);
        if ((lane & 1) == 0) {
            #pragma unroll
            for (int j = 0; j < 8; j++) sh_alpha[w][e][j] = p[j] + b2v[j];
        }
        __syncwarp();
        if (lane < 8) {
            float mx = -1e30f;
            #pragma unroll
            for (int t = 0; t < 16; t++) mx = fmaxf(mx, sh_alpha[w][t][lane]);
            float ex[16], sm = 0.f;
            #pragma unroll
            for (int t = 0; t < 16; t++) { ex[t] = __expf(sh_alpha[w][t][lane]-mx); sm += ex[t]; }
            float inv = 1.f/sm;
            #pragma unroll
            for (int t = 0; t < 16; t++) sh_alpha[w][t][lane] = ex[t]*inv;
        }
        __syncwarp();
        float acc = 0.f, acc2 = 0.f;
        #pragma unroll
        for (int t = 0; t < 16; t++) {
            int sj = __shfl_sync(0xffffffffu, sv, t);
            float hw  = g_hW[sj*64 + c];
            float hw2 = g_hW[sj*64 + c2];
            float d0 = sh_d[w][t][0], d1 = sh_d[w][t][1], d2 = sh_d[w][t][2];
            float al = sh_alpha[w][t][j8];
            acc  = fmaf(al, hw  + fmaf(d0,A0,fmaf(d1,A1,fmaf(d2,A2,Abc))), acc);
            acc2 = fmaf(al, hw2 + fmaf(d0,B0,fmaf(d1,B1,fmaf(d2,B2,Bbc))), acc2);
        }
        g_aggr[n*64 + c]  = acc;
        g_aggr[n*64 + c2] = acc2;
        st += acc; sq += acc*acc; st2 += acc2; sq2 += acc2*acc2;
        __syncwarp();
    }
    __syncthreads();
    atomicAdd(&shS[0][c],  st);  atomicAdd(&shS[1][c],  sq);
    atomicAdd(&shS[0][c2], st2); atomicAdd(&shS[1][c2], sq2);
    __syncthreads();
    if (tid < 64) {
        atomicAdd(&g_sum[256+tid], (double)shS[0][tid]);
        atomicAdd(&g_ssq[256+tid], (double)shS[1][tid]);
    }
}

// ---------------------------------------------------------------------------
__global__ __launch_bounds__(256) void k_final(const float* __restrict__ x,
        const float* __restrict__ g, const float* __restrict__ b,
        float* __restrict__ out) {
    __shared__ float sSc[64], sBi[64];
    int tid = threadIdx.x;
    if (tid < 64) {
        double mu  = g_sum[5*64+tid] * (1.0/NN);
        double var = g_ssq[5*64+tid] * (1.0/NN) - mu*mu;
        float sc = g[tid] * rsqrtf((float)var + BNEPS);
        sSc[tid] = sc; sBi[tid] = b[tid] - (float)mu*sc;
    }
    __syncthreads();
    int stride = gridDim.x * blockDim.x;
    for (int i4 = blockIdx.x*blockDim.x + tid; i4 < NN*16; i4 += stride) {
        float4 v  = *(const float4*)&g_t3[i4*4];
        float4 xv = *(const float4*)&x[i4*4];
        int cg = (i4 & 15) * 4;
        float4 r;
        r.x = fmaxf(fmaf(v.x, sSc[cg+0], sBi[cg+0]) + xv.x, 0.f);
        r.y = fmaxf(fmaf(v.y, sSc[cg+1], sBi[cg+1]) + xv.y, 0.f);
        r.z = fmaxf(fmaf(v.z, sSc[cg+2], sBi[cg+2]) + xv.z, 0.f);
        r.w = fmaxf(fmaf(v.w, sSc[cg+3], sBi[cg+3]) + xv.w, 0.f);
        *(float4*)&out[i4*4] = r;
    }
}

// ---------------------------------------------------------------------------
extern "C" void kernel_launch(void* const* d_in, const int* in_sizes, int n_in,
                              void* d_out, int out_size) {
    const float* x      = (const float*)d_in[0];
    const float* pos    = (const float*)d_in[1];
    const int*   src    = (const int*)  d_in[2];
    const float* W_in   = (const float*)d_in[3];
    const float* W_out  = (const float*)d_in[4];
    const float* pw1    = (const float*)d_in[5];
    const float* pb1    = (const float*)d_in[6];
    const float* pbn_g  = (const float*)d_in[7];
    const float* pbn_b  = (const float*)d_in[8];
    const float* pw2    = (const float*)d_in[9];
    const float* pb2    = (const float*)d_in[10];
    const float* abn1_g = (const float*)d_in[11];
    const float* abn1_b = (const float*)d_in[12];
    const float* aw1    = (const float*)d_in[13];
    const float* ab1    = (const float*)d_in[14];
    const float* abn2_g = (const float*)d_in[15];
    const float* abn2_b = (const float*)d_in[16];
    const float* aw2    = (const float*)d_in[17];
    const float* ab2    = (const float*)d_in[18];
    const float* lin_w  = (const float*)d_in[19];
    const float* lin_b  = (const float*)d_in[20];
    const float* src_w  = (const float*)d_in[21];
    const float* src_b  = (const float*)d_in[22];
    const float* dst_w  = (const float*)d_in[23];
    const float* dst_b  = (const float*)d_in[24];
    const float* bn1_g  = (const float*)d_in[25];
    const float* bn1_b  = (const float*)d_in[26];
    const float* bn2_g  = (const float*)d_in[27];
    const float* bn2_b  = (const float*)d_in[28];
    const float* bn3_g  = (const float*)d_in[29];
    const float* bn3_b  = (const float*)d_in[30];
    float* out = (float*)d_out;

    float *p_t, *p_asrc, *p_adst, *p_hW, *p_aggr, *p_t3;
    cudaGetSymbolAddress((void**)&p_t,    g_t);
    cudaGetSymbolAddress((void**)&p_asrc, g_asrc);
    cudaGetSymbolAddress((void**)&p_adst, g_adst);
    cudaGetSymbolAddress((void**)&p_hW,   g_hW);
    cudaGetSymbolAddress((void**)&p_aggr, g_aggr);
    cudaGetSymbolAddress((void**)&p_t3,   g_t3);

    k_zero<<<1,384>>>();

    // pos MLP raw outputs + posBN stats
    k_pos_stats<<<1024,256>>>(pos, src, pw1, pb1);

    // t = x @ W_in^T (+ bn1 stats)
    k_gemm<<<512,256>>>(x, W_in, nullptr, p_t,
                        nullptr, nullptr, nullptr, nullptr, nullptr, nullptr,
                        -1, nullptr, nullptr, 0);

    // a_src/a_dst/hW = relu(bn1(t)) @ {src_w,dst_w,lin_w}^T + bias (fused triple)
    k_gemm<<<512,256>>>(p_t, src_w, src_b, p_asrc,
                        dst_w, dst_b, p_adst,
                        lin_w, lin_b, p_hW,
                        0, bn1_g, bn1_b, -1);

    // attn_bn1 stats over edges
    k_attn1_stats<<<1024,256>>>(src, pw2, pb2, pbn_g, pbn_b);

    // a1 ; attn_bn2 stats
    k_a1<<<1024,256>>>(src, pw2, pb2, aw1, ab1, pbn_g, pbn_b, abn1_g, abn1_b);

    // softmax + aggregation ; bn2 stats
    k_aggr<<<1024,256>>>(src, pw2, pb2, aw2, ab2, pbn_g, pbn_b, abn2_g, abn2_b);

    // t3 = relu(bn2(aggr)) @ W_out^T ; bn3 stats
    k_gemm<<<512,256>>>(p_aggr, W_out, nullptr, p_t3,
                        nullptr, nullptr, nullptr, nullptr, nullptr, nullptr,
                        4, bn2_g, bn2_b, 5);

    // y = relu(bn3(t3) + x)
    k_final<<<1024,256>>>(x, bn3_g, bn3_b, out);
}